// round 15
// baseline (speedup 1.0000x reference)
#include <cuda_runtime.h>
#include <math.h>
#include <stdint.h>

constexpr long MTOK  = 16 * 512;     // 8192 tokens

// ---------------------------------------------------------------------------
// Scratch arena
// ---------------------------------------------------------------------------
constexpr long OFF_X    = 0;
constexpr long OFF_LN   = OFF_X    + MTOK * 256;
constexpr long OFF_B256 = OFF_LN   + MTOK * 256;
constexpr long OFF_XZ   = OFF_B256 + MTOK * 256;
constexpr long OFF_XC   = OFF_XZ   + 2 * MTOK * 512;
constexpr long OFF_DBC  = OFF_XC   + 2 * MTOK * 256;
constexpr long OFF_DT   = OFF_DBC  + 2 * MTOK * 40;
constexpr long OFF_Y    = OFF_DT   + 2 * MTOK * 256;
constexpr long OFF_FF   = OFF_Y    + 2 * MTOK * 256;
constexpr long OFF_W2C  = OFF_FF   + MTOK * 1024;
constexpr long OFF_WXZ  = OFF_W2C  + 24L * 256 * 256;
constexpr long OFF_BXZ  = OFF_WXZ  + 24L * 256 * 512;
constexpr long TOTAL_F  = OFF_BXZ  + 24L * 512;

__device__ float g_buf[TOTAL_F];

__device__ __forceinline__ uint32_t smem_u32(const void* p)
{
    return (uint32_t)__cvta_generic_to_shared(p);
}

// ---------------------------------------------------------------------------
// Embedding: x = LN(ids @ proj_w + proj_b)  (runs once)
// ---------------------------------------------------------------------------
__global__ void embed_ln_kernel(const float* __restrict__ ids,
                                const float* __restrict__ pw,
                                const float* __restrict__ pb,
                                const float* __restrict__ gam,
                                const float* __restrict__ bet,
                                float* __restrict__ x)
{
    __shared__ float sin[32];
    __shared__ float sred[8];
    int m = blockIdx.x, d = threadIdx.x;
    if (d < 32) sin[d] = ids[(long)m * 32 + d];
    __syncthreads();
    float v = pb[d];
#pragma unroll
    for (int e = 0; e < 32; e++)
        v = fmaf(sin[e], pw[e * 256 + d], v);
    float s = v;
#pragma unroll
    for (int o = 16; o > 0; o >>= 1) s += __shfl_xor_sync(0xffffffffu, s, o);
    if ((d & 31) == 0) sred[d >> 5] = s;
    __syncthreads();
    float mean = 0.f;
#pragma unroll
    for (int i = 0; i < 8; i++) mean += sred[i];
    mean *= (1.f / 256.f);
    float c = v - mean;
    float q = c * c;
#pragma unroll
    for (int o = 16; o > 0; o >>= 1) q += __shfl_xor_sync(0xffffffffu, q, o);
    __syncthreads();
    if ((d & 31) == 0) sred[d >> 5] = q;
    __syncthreads();
    float var = 0.f;
#pragma unroll
    for (int i = 0; i < 8; i++) var += sred[i];
    var *= (1.f / 256.f);
    x[(long)m * 256 + d] = c * rsqrtf(var + 1e-5f) * gam[d] + bet[d];
}

// ---------------------------------------------------------------------------
// Warp-level LN helper on 8 registers
// ---------------------------------------------------------------------------
__device__ __forceinline__ void warp_ln8(float* a,
                                         const float* __restrict__ gam,
                                         const float* __restrict__ bet,
                                         int lane, float* o)
{
    float s = 0.f;
#pragma unroll
    for (int i = 0; i < 8; i++) s += a[i];
#pragma unroll
    for (int off = 16; off > 0; off >>= 1) s += __shfl_xor_sync(0xffffffffu, s, off);
    float mean = s * (1.f / 256.f);
    float q = 0.f;
#pragma unroll
    for (int i = 0; i < 8; i++) {
        float c = a[i] - mean;
        q = fmaf(c, c, q);
    }
#pragma unroll
    for (int off = 16; off > 0; off >>= 1) q += __shfl_xor_sync(0xffffffffu, q, off);
    float inv = rsqrtf(q * (1.f / 256.f) + 1e-5f);
    const float4* gp = (const float4*)(gam + lane * 8);
    const float4* bp = (const float4*)(bet + lane * 8);
    float4 g0 = gp[0], g1 = gp[1], b0 = bp[0], b1 = bp[1];
    o[0] = (a[0] - mean) * inv * g0.x + b0.x;
    o[1] = (a[1] - mean) * inv * g0.y + b0.y;
    o[2] = (a[2] - mean) * inv * g0.z + b0.z;
    o[3] = (a[3] - mean) * inv * g0.w + b0.w;
    o[4] = (a[4] - mean) * inv * g1.x + b1.x;
    o[5] = (a[5] - mean) * inv * g1.y + b1.y;
    o[6] = (a[6] - mean) * inv * g1.z + b1.z;
    o[7] = (a[7] - mean) * inv * g1.w + b1.w;
}

// ---------------------------------------------------------------------------
// Warp-per-token LayerNorm, optional residual.
// ---------------------------------------------------------------------------
__global__ void __launch_bounds__(256)
ln_kernel(const float* __restrict__ in,
          const float* __restrict__ res,
          const float* __restrict__ gam,
          const float* __restrict__ bet,
          float* __restrict__ out)
{
    int w = threadIdx.x >> 5, lane = threadIdx.x & 31;
    long m = (long)blockIdx.x * 8 + w;
    const float4* ip = (const float4*)(in + m * 256);
    float4 v0 = ip[lane * 2];
    float4 v1 = ip[lane * 2 + 1];
    if (res) {
        const float4* rp = (const float4*)(res + m * 256);
        float4 r0 = rp[lane * 2];
        float4 r1 = rp[lane * 2 + 1];
        v0.x += r0.x; v0.y += r0.y; v0.z += r0.z; v0.w += r0.w;
        v1.x += r1.x; v1.y += r1.y; v1.z += r1.z; v1.w += r1.w;
    }
    float a[8] = {v0.x, v0.y, v0.z, v0.w, v1.x, v1.y, v1.z, v1.w};
    float o[8];
    warp_ln8(a, gam, bet, lane, o);
    float4* op = (float4*)(out + m * 256);
    op[lane * 2]     = make_float4(o[0], o[1], o[2], o[3]);
    op[lane * 2 + 1] = make_float4(o[4], o[5], o[6], o[7]);
}

// ---------------------------------------------------------------------------
// Fused LN3 + LN1(next layer)
// ---------------------------------------------------------------------------
__global__ void __launch_bounds__(256)
ln3ln1_kernel(const float* __restrict__ in,
              const float* __restrict__ res,
              const float* __restrict__ g3,
              const float* __restrict__ b3,
              const float* __restrict__ g1,
              const float* __restrict__ b1,
              float* __restrict__ xout,
              float* __restrict__ lnb)
{
    int w = threadIdx.x >> 5, lane = threadIdx.x & 31;
    long m = (long)blockIdx.x * 8 + w;
    const float4* ip = (const float4*)(in + m * 256);
    const float4* rp = (const float4*)(res + m * 256);
    float4 v0 = ip[lane * 2], v1 = ip[lane * 2 + 1];
    float4 r0 = rp[lane * 2], r1 = rp[lane * 2 + 1];
    float a[8] = {v0.x + r0.x, v0.y + r0.y, v0.z + r0.z, v0.w + r0.w,
                  v1.x + r1.x, v1.y + r1.y, v1.z + r1.z, v1.w + r1.w};
    float o[8];
    warp_ln8(a, g3, b3, lane, o);
    float4* xp = (float4*)(xout + m * 256);
    xp[lane * 2]     = make_float4(o[0], o[1], o[2], o[3]);
    xp[lane * 2 + 1] = make_float4(o[4], o[5], o[6], o[7]);
    if (lnb) {
        float o2[8];
        warp_ln8(o, g1, b1, lane, o2);
        float4* lp = (float4*)(lnb + m * 256);
        lp[lane * 2]     = make_float4(o2[0], o2[1], o2[2], o2[3]);
        lp[lane * 2 + 1] = make_float4(o2[4], o2[5], o2[6], o2[7]);
    }
}

// ---------------------------------------------------------------------------
// bias composition: bxz[lg][n] = sum_j ipb[l][g*128+j] * inw[lg][j][n]
// 4 lanes per output; shuffle reduce.
// ---------------------------------------------------------------------------
__global__ void bxz_kernel(const float* __restrict__ ipb,
                           const float* __restrict__ inw,
                           float* __restrict__ bxz)
{
    int idx = blockIdx.x * 256 + threadIdx.x;   // 0 .. 24*512*4-1
    int o = idx >> 2;                            // output index
    int p = idx & 3;                             // partial index
    int lg = o >> 9;
    int n = o & 511;
    int l = lg >> 1, g = lg & 1;
    const float* bp = ipb + l * 256 + g * 128 + p * 32;
    const float* wp = inw + (long)lg * 65536 + (long)(p * 32) * 512 + n;
    float s = 0.f;
#pragma unroll 8
    for (int j = 0; j < 32; j++)
        s = fmaf(bp[j], wp[(long)j * 512], s);
    s += __shfl_xor_sync(0xffffffffu, s, 1);
    s += __shfl_xor_sync(0xffffffffu, s, 2);
    if (p == 0) bxz[o] = s;
}

// ---------------------------------------------------------------------------
// TF32 GEMM, 256 threads, 128x128 tile, BK=32, 3-stage pipeline, 1 barrier.
// lda runtime. AREV: reverse A rows within each 512-token batch for g==1.
// bias per-group stride sBg.
// ---------------------------------------------------------------------------
template<int ACT, bool AREV>
__global__ void __launch_bounds__(256, 2)
tf128_kernel(const float* __restrict__ A,
             const float* __restrict__ W,
             const float* __restrict__ bias,
             float* __restrict__ C,
             int M, int N, int K, int lda,
             long sAg, long sWg, long sCg, long sBg)
{
    extern __shared__ uint32_t dyn[];
    constexpr int AW = 128 * 36;
    constexpr int SW = AW + 32 * 136;

    int g = blockIdx.z;
    A += (long)g * sAg;
    W += (long)g * sWg;
    C += (long)g * sCg;
    if (bias) bias += (long)g * sBg;
    bool rev = AREV && (g == 1);

    int tid  = threadIdx.x;
    int warp = tid >> 5;
    int lane = tid & 31;
    int wm = (warp & 1) * 64;
    int wn = (warp >> 1) * 32;
    int gID = lane >> 2;
    int tig = lane & 3;
    int rowBase = blockIdx.y * 128;
    int colBase = blockIdx.x * 128;

    const float* Wbase = W + colBase;

    auto stage = [&](int buf, int k0) {
        uint32_t* As = dyn + buf * SW;
        uint32_t* Bs = dyn + buf * SW + AW;
#pragma unroll
        for (int it = 0; it < 4; it++) {
            int f = tid + it * 256;
            int r = f >> 3, k4 = (f & 7) * 4;
            int m = rowBase + r;
            if (rev) m = (m & ~511) + 511 - (m & 511);
            asm volatile("cp.async.ca.shared.global [%0], [%1], 16;\n"
                         :: "r"(smem_u32(&As[r * 36 + k4])),
                            "l"(A + (long)m * lda + k0 + k4));
        }
#pragma unroll
        for (int it = 0; it < 4; it++) {
            int f = tid + it * 256;
            int kr = f >> 5, n4 = (f & 31) * 4;
            asm volatile("cp.async.ca.shared.global [%0], [%1], 16;\n"
                         :: "r"(smem_u32(&Bs[kr * 136 + n4])),
                            "l"(Wbase + (long)(k0 + kr) * N + n4));
        }
        asm volatile("cp.async.commit_group;\n");
    };

    float acc[4][4][4];
#pragma unroll
    for (int a = 0; a < 4; a++)
#pragma unroll
        for (int b = 0; b < 4; b++)
#pragma unroll
            for (int c = 0; c < 4; c++) acc[a][b][c] = 0.f;

    auto compute = [&](int buf) {
        uint32_t* As = dyn + buf * SW;
        uint32_t* Bs = dyn + buf * SW + AW;
#pragma unroll
        for (int ks = 0; ks < 32; ks += 8) {
            uint32_t bf[4][2];
#pragma unroll
            for (int nt = 0; nt < 4; nt++) {
                int col = wn + nt * 8 + gID;
                bf[nt][0] = Bs[(ks + tig) * 136 + col];
                bf[nt][1] = Bs[(ks + tig + 4) * 136 + col];
            }
#pragma unroll
            for (int mt = 0; mt < 4; mt++) {
                int row = wm + mt * 16 + gID;
                uint32_t a0 = As[row * 36 + ks + tig] + 0x1000u;
                uint32_t a1 = As[(row + 8) * 36 + ks + tig] + 0x1000u;
                uint32_t a2 = As[row * 36 + ks + tig + 4] + 0x1000u;
                uint32_t a3 = As[(row + 8) * 36 + ks + tig + 4] + 0x1000u;
#pragma unroll
                for (int nt = 0; nt < 4; nt++) {
                    asm volatile(
                        "mma.sync.aligned.m16n8k8.row.col.f32.tf32.tf32.f32 "
                        "{%0,%1,%2,%3}, {%4,%5,%6,%7}, {%8,%9}, {%0,%1,%2,%3};\n"
                        : "+f"(acc[mt][nt][0]), "+f"(acc[mt][nt][1]),
                          "+f"(acc[mt][nt][2]), "+f"(acc[mt][nt][3])
                        : "r"(a0), "r"(a1), "r"(a2), "r"(a3),
                          "r"(bf[nt][0]), "r"(bf[nt][1]));
                }
            }
        }
    };

    int nk = K >> 5;
    stage(0, 0);
    if (nk > 1) stage(1, 32);
    for (int ki = 0; ki < nk; ki++) {
        if (ki < nk - 1) asm volatile("cp.async.wait_group 1;\n");
        else             asm volatile("cp.async.wait_group 0;\n");
        __syncthreads();
        int kn = ki + 2;
        if (kn < nk) stage(kn % 3, kn << 5);
        compute(ki % 3);
    }

#pragma unroll
    for (int mt = 0; mt < 4; mt++) {
        int row0 = rowBase + wm + mt * 16 + gID;
#pragma unroll
        for (int nt = 0; nt < 4; nt++) {
            int col = colBase + wn + nt * 8 + tig * 2;
            float b0 = 0.f, b1 = 0.f;
            if (bias) { b0 = bias[col]; b1 = bias[col + 1]; }
            float v[4];
            v[0] = acc[mt][nt][0] + b0;
            v[1] = acc[mt][nt][1] + b1;
            v[2] = acc[mt][nt][2] + b0;
            v[3] = acc[mt][nt][3] + b1;
            if (ACT == 2) {
#pragma unroll
                for (int q = 0; q < 4; q++)
                    v[q] = 0.5f * v[q] * (1.f + erff(v[q] * 0.70710678118654752f));
            }
            *(float2*)&C[(long)row0 * N + col] = make_float2(v[0], v[1]);
            *(float2*)&C[(long)(row0 + 8) * N + col] = make_float2(v[2], v[3]);
        }
    }
}

// ---------------------------------------------------------------------------
// TF32 GEMM, 256 threads, 64x128 tile (plain store; dbc+dt fusion)
// ---------------------------------------------------------------------------
template<int ACT, bool NG, bool DTF>
__global__ void __launch_bounds__(256, 2)
tf64_kernel(const float* __restrict__ A,
            const float* __restrict__ W,
            const float* __restrict__ bias,
            float* __restrict__ C,
            int M, int N, int K,
            long sAg, long sWg, long sCg,
            const float* __restrict__ dtw,
            const float* __restrict__ dtb,
            float* __restrict__ DTout)
{
    extern __shared__ uint32_t dyn[];
    constexpr int AW = 64 * 36;
    constexpr int SW = AW + 32 * 136;

    int g = blockIdx.z;
    A += (long)g * sAg;
    W += (long)g * sWg;
    C += (long)g * sCg;
    if (DTF) {
        dtw += (long)g * 2048;
        dtb += (long)g * 256;
        DTout += (long)g * MTOK * 256;
    }

    int tid  = threadIdx.x;
    int warp = tid >> 5;
    int lane = tid & 31;
    int wm = (warp & 1) * 32;
    int wn = (warp >> 1) * 32;
    int gID = lane >> 2;
    int tig = lane & 3;
    int rowBase = blockIdx.y * 64;
    int colBase = blockIdx.x * 128;

    const float* Abase = A + (long)rowBase * K;
    const float* Wbase = W + colBase;

    if (NG) {
#pragma unroll
        for (int s = 0; s < 3; s++) {
            uint32_t* Bs = dyn + s * SW + AW;
            for (int f = tid; f < 1024; f += 256) {
                int kr = f >> 5, n4 = (f & 31) * 4;
                if (n4 + 4 > N)
                    *(uint4*)&Bs[kr * 136 + n4] = make_uint4(0, 0, 0, 0);
            }
        }
        __syncthreads();
    }

    auto stage = [&](int buf, int k0) {
        uint32_t* As = dyn + buf * SW;
        uint32_t* Bs = dyn + buf * SW + AW;
#pragma unroll
        for (int it = 0; it < 2; it++) {
            int f = tid + it * 256;
            int r = f >> 3, k4 = (f & 7) * 4;
            asm volatile("cp.async.ca.shared.global [%0], [%1], 16;\n"
                         :: "r"(smem_u32(&As[r * 36 + k4])),
                            "l"(Abase + (long)r * K + k0 + k4));
        }
#pragma unroll
        for (int it = 0; it < 4; it++) {
            int f = tid + it * 256;
            int kr = f >> 5, n4 = (f & 31) * 4;
            if (!NG || n4 + 4 <= N)
                asm volatile("cp.async.ca.shared.global [%0], [%1], 16;\n"
                             :: "r"(smem_u32(&Bs[kr * 136 + n4])),
                                "l"(Wbase + (long)(k0 + kr) * N + n4));
        }
        asm volatile("cp.async.commit_group;\n");
    };

    float acc[2][4][4];
#pragma unroll
    for (int a = 0; a < 2; a++)
#pragma unroll
        for (int b = 0; b < 4; b++)
#pragma unroll
            for (int c = 0; c < 4; c++) acc[a][b][c] = 0.f;

    auto compute = [&](int buf) {
        uint32_t* As = dyn + buf * SW;
        uint32_t* Bs = dyn + buf * SW + AW;
#pragma unroll
        for (int ks = 0; ks < 32; ks += 8) {
            uint32_t bf[4][2];
#pragma unroll
            for (int nt = 0; nt < 4; nt++) {
                int col = wn + nt * 8 + gID;
                bf[nt][0] = Bs[(ks + tig) * 136 + col];
                bf[nt][1] = Bs[(ks + tig + 4) * 136 + col];
            }
#pragma unroll
            for (int mt = 0; mt < 2; mt++) {
                int row = wm + mt * 16 + gID;
                uint32_t a0 = As[row * 36 + ks + tig] + 0x1000u;
                uint32_t a1 = As[(row + 8) * 36 + ks + tig] + 0x1000u;
                uint32_t a2 = As[row * 36 + ks + tig + 4] + 0x1000u;
                uint32_t a3 = As[(row + 8) * 36 + ks + tig + 4] + 0x1000u;
#pragma unroll
                for (int nt = 0; nt < 4; nt++) {
                    asm volatile(
                        "mma.sync.aligned.m16n8k8.row.col.f32.tf32.tf32.f32 "
                        "{%0,%1,%2,%3}, {%4,%5,%6,%7}, {%8,%9}, {%0,%1,%2,%3};\n"
                        : "+f"(acc[mt][nt][0]), "+f"(acc[mt][nt][1]),
                          "+f"(acc[mt][nt][2]), "+f"(acc[mt][nt][3])
                        : "r"(a0), "r"(a1), "r"(a2), "r"(a3),
                          "r"(bf[nt][0]), "r"(bf[nt][1]));
                }
            }
        }
    };

    int nk = K >> 5;
    stage(0, 0);
    if (nk > 1) stage(1, 32);
    for (int ki = 0; ki < nk; ki++) {
        if (ki < nk - 1) asm volatile("cp.async.wait_group 1;\n");
        else             asm volatile("cp.async.wait_group 0;\n");
        __syncthreads();
        int kn = ki + 2;
        if (kn < nk) stage(kn % 3, kn << 5);
        compute(ki % 3);
    }

#pragma unroll
    for (int mt = 0; mt < 2; mt++) {
        int row0 = rowBase + wm + mt * 16 + gID;
#pragma unroll
        for (int nt = 0; nt < 4; nt++) {
            int col = colBase + wn + nt * 8 + tig * 2;
            if (NG && col >= N) continue;
            float b0 = 0.f, b1 = 0.f;
            if (bias) { b0 = bias[col]; b1 = bias[col + 1]; }
            float v[4];
            v[0] = acc[mt][nt][0] + b0;
            v[1] = acc[mt][nt][1] + b1;
            v[2] = acc[mt][nt][2] + b0;
            v[3] = acc[mt][nt][3] + b1;
            if (ACT == 2) {
#pragma unroll
                for (int q = 0; q < 4; q++)
                    v[q] = 0.5f * v[q] * (1.f + erff(v[q] * 0.70710678118654752f));
            }
            *(float2*)&C[(long)row0 * N + col] = make_float2(v[0], v[1]);
            *(float2*)&C[(long)(row0 + 8) * N + col] = make_float2(v[2], v[3]);
        }
    }

    if (DTF) {
        float* dbs = (float*)(dyn + 3 * SW);
        if (warp < 2) {
            int col = tig * 2;
#pragma unroll
            for (int mt = 0; mt < 2; mt++) {
#pragma unroll
                for (int h = 0; h < 2; h++) {
                    int rl = wm + mt * 16 + gID + h * 8;
                    dbs[rl * 8 + col]     = acc[mt][0][h * 2];
                    dbs[rl * 8 + col + 1] = acc[mt][0][h * 2 + 1];
                }
            }
        }
        __syncthreads();
        int d = tid;
        float wreg[8];
#pragma unroll
        for (int r = 0; r < 8; r++) wreg[r] = dtw[r * 256 + d];
        float bb = dtb[d];
        float* dto = DTout + (long)rowBase * 256 + d;
        for (int r = 0; r < 64; r++) {
            float s = bb;
#pragma unroll
            for (int j = 0; j < 8; j++) s = fmaf(dbs[r * 8 + j], wreg[j], s);
            s = (s > 20.f) ? s : log1pf(expf(s));
            dto[(long)r * 256] = s;
        }
    }
}

// ---------------------------------------------------------------------------
// Fused out-projection: C = y0 @ Wc[0] + y1[rev] @ Wc[1] + bias  ([M,256])
// Wc: composed [2][256][256]. 64x128 tile, 16 K-slabs (2 groups x 8).
// ---------------------------------------------------------------------------
__global__ void __launch_bounds__(256, 2)
outop_kernel(const float* __restrict__ Y,
             const float* __restrict__ Wc,
             const float* __restrict__ bias,
             float* __restrict__ C)
{
    extern __shared__ uint32_t dyn[];
    constexpr int AW = 64 * 36;
    constexpr int SW = AW + 32 * 136;
    constexpr int N = 256;

    int tid  = threadIdx.x;
    int warp = tid >> 5;
    int lane = tid & 31;
    int wm = (warp & 1) * 32;
    int wn = (warp >> 1) * 32;
    int gID = lane >> 2;
    int tig = lane & 3;
    int rowBase = blockIdx.y * 64;
    int colBase = blockIdx.x * 128;

    auto stage = [&](int buf, int s) {
        int g = s >> 3;
        int k0 = (s & 7) << 5;
        const float* Ab = Y + (long)g * MTOK * 256;
        const float* Wb = Wc + (long)g * 65536 + colBase;
        uint32_t* As = dyn + buf * SW;
        uint32_t* Bs = dyn + buf * SW + AW;
#pragma unroll
        for (int it = 0; it < 2; it++) {
            int f = tid + it * 256;
            int r = f >> 3, k4 = (f & 7) * 4;
            int m = rowBase + r;
            if (g) m = (m & ~511) + 511 - (m & 511);
            asm volatile("cp.async.ca.shared.global [%0], [%1], 16;\n"
                         :: "r"(smem_u32(&As[r * 36 + k4])),
                            "l"(Ab + (long)m * 256 + k0 + k4));
        }
#pragma unroll
        for (int it = 0; it < 4; it++) {
            int f = tid + it * 256;
            int kr = f >> 5, n4 = (f & 31) * 4;
            asm volatile("cp.async.ca.shared.global [%0], [%1], 16;\n"
                         :: "r"(smem_u32(&Bs[kr * 136 + n4])),
                            "l"(Wb + (long)(k0 + kr) * N + n4));
        }
        asm volatile("cp.async.commit_group;\n");
    };

    float acc[2][4][4];
#pragma unroll
    for (int a = 0; a < 2; a++)
#pragma unroll
        for (int b = 0; b < 4; b++)
#pragma unroll
            for (int c = 0; c < 4; c++) acc[a][b][c] = 0.f;

    auto compute = [&](int buf) {
        uint32_t* As = dyn + buf * SW;
        uint32_t* Bs = dyn + buf * SW + AW;
#pragma unroll
        for (int ks = 0; ks < 32; ks += 8) {
            uint32_t bf[4][2];
#pragma unroll
            for (int nt = 0; nt < 4; nt++) {
                int col = wn + nt * 8 + gID;
                bf[nt][0] = Bs[(ks + tig) * 136 + col];
                bf[nt][1] = Bs[(ks + tig + 4) * 136 + col];
            }
#pragma unroll
            for (int mt = 0; mt < 2; mt++) {
                int row = wm + mt * 16 + gID;
                uint32_t a0 = As[row * 36 + ks + tig] + 0x1000u;
                uint32_t a1 = As[(row + 8) * 36 + ks + tig] + 0x1000u;
                uint32_t a2 = As[row * 36 + ks + tig + 4] + 0x1000u;
                uint32_t a3 = As[(row + 8) * 36 + ks + tig + 4] + 0x1000u;
#pragma unroll
                for (int nt = 0; nt < 4; nt++) {
                    asm volatile(
                        "mma.sync.aligned.m16n8k8.row.col.f32.tf32.tf32.f32 "
                        "{%0,%1,%2,%3}, {%4,%5,%6,%7}, {%8,%9}, {%0,%1,%2,%3};\n"
                        : "+f"(acc[mt][nt][0]), "+f"(acc[mt][nt][1]),
                          "+f"(acc[mt][nt][2]), "+f"(acc[mt][nt][3])
                        : "r"(a0), "r"(a1), "r"(a2), "r"(a3),
                          "r"(bf[nt][0]), "r"(bf[nt][1]));
                }
            }
        }
    };

    stage(0, 0);
    stage(1, 1);
    for (int s = 0; s < 16; s++) {
        if (s < 15) asm volatile("cp.async.wait_group 1;\n");
        else        asm volatile("cp.async.wait_group 0;\n");
        __syncthreads();
        int sn = s + 2;
        if (sn < 16) stage(sn % 3, sn);
        compute(s % 3);
    }

#pragma unroll
    for (int mt = 0; mt < 2; mt++) {
        int row0 = rowBase + wm + mt * 16 + gID;
#pragma unroll
        for (int nt = 0; nt < 4; nt++) {
            int col = colBase + wn + nt * 8 + tig * 2;
            float b0 = bias[col], b1 = bias[col + 1];
            *(float2*)&C[(long)row0 * N + col] =
                make_float2(acc[mt][nt][0] + b0, acc[mt][nt][1] + b1);
            *(float2*)&C[(long)(row0 + 8) * N + col] =
                make_float2(acc[mt][nt][2] + b0, acc[mt][nt][3] + b1);
        }
    }
}

// ---------------------------------------------------------------------------
// depthwise causal conv (K=4) + bias + silu; 4 t-outputs per thread
// ---------------------------------------------------------------------------
__global__ void conv_silu_kernel(const float* __restrict__ xz,
                                 const float* __restrict__ convw,
                                 const float* __restrict__ convb,
                                 float* __restrict__ xc)
{
    long i = (long)blockIdx.x * 256 + threadIdx.x;
    if (i >= 2 * MTOK * 64) return;
    int d = (int)(i & 255);
    long q = i >> 8;
    int t0 = (int)(q & 127) * 4;
    int b  = (int)((q >> 7) & 15);
    int g  = (int)(q >> 11);

    const float4 w4 = *(const float4*)(convw + ((long)g * 256 + d) * 4);
    float bias = convb[(long)g * 256 + d];

    long mrow = (long)g * MTOK + (long)b * 512 + t0;
    const float* xp = xz + mrow * 512 + d;
    float xv[7];
#pragma unroll
    for (int j = 0; j < 7; j++) {
        int t = t0 - 3 + j;
        xv[j] = (t >= 0) ? xp[(long)(j - 3) * 512] : 0.f;
    }
    float* op = xc + mrow * 256 + d;
#pragma unroll
    for (int j = 0; j < 4; j++) {
        float acc = bias;
        acc = fmaf(xv[j],     w4.x, acc);
        acc = fmaf(xv[j + 1], w4.y, acc);
        acc = fmaf(xv[j + 2], w4.z, acc);
        acc = fmaf(xv[j + 3], w4.w, acc);
        op[(long)j * 256] = acc / (1.f + __expf(-acc));
    }
}

// ---------------------------------------------------------------------------
// Selective scan, 8 lanes per (g,b,d) group, 2 states per lane, pipelined.
// ---------------------------------------------------------------------------
__global__ void __launch_bounds__(256)
scan_kernel(const float* __restrict__ dt,
            const float* __restrict__ xc,
            const float* __restrict__ dbc,
            const float* __restrict__ xz,
            const float* __restrict__ alog,
            const float* __restrict__ dpar,
            float* __restrict__ y)
{
    int gidx = blockIdx.x * 32 + (threadIdx.x >> 3);
    int li = threadIdx.x & 7;
    int g = gidx >> 12;
    int b = (gidx >> 8) & 15;
    int d = gidx & 255;

    const float2 al = *(const float2*)&alog[((long)(g * 256 + d)) * 16 + li * 2];
    const float L2E = 1.4426950408889634f;
    float A0 = -__expf(al.x) * L2E;
    float A1 = -__expf(al.y) * L2E;
    float dp = dpar[(long)g * 256 + d];

    long mbase = (long)g * MTOK + (long)b * 512;
    const float* dtp = dt + mbase * 256 + d;
    const float* xcp = xc + mbase * 256 + d;
    const float* dbp = dbc + mbase * 40;
    const float* zp  = xz + mbase * 512 + 256 + d;
    float* yp = y + mbase * 256 + d;

    float h0 = 0.f, h1 = 0.f;

    float dtv_n = dtp[0];
    float xv_n  = xcp[0];
    float z_n   = zp[0];
    float2 B_n  = *(const float2*)&dbp[8 + li * 2];
    float2 C_n  = *(const float2*)&dbp[24 + li * 2];

    for (int t = 0; t < 512; t++) {
        float dtv = dtv_n, xv = xv_n, z = z_n;
        float2 Bv = B_n, Cv = C_n;
        long tn = (t + 1 < 512) ? t + 1 : 511;
        dtv_n = dtp[tn * 256];
        xv_n  = xcp[tn * 256];
        z_n   = zp[tn * 512];
        B_n   = *(const float2*)&dbp[tn * 40 + 8 + li * 2];
        C_n   = *(const float2*)&dbp[tn * 40 + 24 + li * 2];

        float dx = dtv * xv;
        h0 = exp2f(dtv * A0) * h0 + dx * Bv.x;
        h1 = exp2f(dtv * A1) * h1 + dx * Bv.y;
        float p = h0 * Cv.x + h1 * Cv.y;
        p += __shfl_xor_sync(0xffffffffu, p, 4);
        p += __shfl_xor_sync(0xffffffffu, p, 2);
        p += __shfl_xor_sync(0xffffffffu, p, 1);
        if (li == 0) {
            float sz = z / (1.f + __expf(-z));
            yp[(long)t * 256] = (p + dp * xv) * sz;
        }
    }
}

// ---------------------------------------------------------------------------
// Launch helpers
// ---------------------------------------------------------------------------
constexpr int SMEM128 = 3 * (128 * 36 + 32 * 136) * 4;
constexpr int SMEM64  = 3 * (64 * 36 + 32 * 136) * 4 + 2048;

template<int ACT, bool AREV>
static void launch_tf128(const float* A, const float* W, const float* bias, float* C,
                         int M, int N, int K, int lda, int G,
                         long sAg, long sWg, long sCg, long sBg)
{
    cudaFuncSetAttribute(tf128_kernel<ACT, AREV>,
                         cudaFuncAttributeMaxDynamicSharedMemorySize, SMEM128);
    dim3 grid(N / 128, M / 128, G);
    tf128_kernel<ACT, AREV><<<grid, 256, SMEM128>>>(A, W, bias, C, M, N, K, lda,
                                                    sAg, sWg, sCg, sBg);
}

template<int ACT, bool NG, bool DTF>
static void launch_tf64(const float* A, const float* W, const float* bias, float* C,
                        int M, int N, int K, int G,
                        long sAg, long sWg, long sCg,
                        const float* dtw = nullptr, const float* dtb = nullptr,
                        float* DTout = nullptr)
{
    cudaFuncSetAttribute(tf64_kernel<ACT, NG, DTF>,
                         cudaFuncAttributeMaxDynamicSharedMemorySize, SMEM64);
    dim3 grid((N + 127) / 128, M / 64, G);
    tf64_kernel<ACT, NG, DTF><<<grid, 256, SMEM64>>>(
        A, W, bias, C, M, N, K, sAg, sWg, sCg, dtw, dtb, DTout);
}

extern "C" void kernel_launch(void* const* d_in, const int* in_sizes, int n_in,
                              void* d_out, int out_size)
{
    const float* input_ids = (const float*)d_in[0];
    const float* proj_w    = (const float*)d_in[1];
    const float* proj_b    = (const float*)d_in[2];
    const float* ln0_g     = (const float*)d_in[3];
    const float* ln0_b     = (const float*)d_in[4];
    const float* ln1_g     = (const float*)d_in[5];
    const float* ln1_b     = (const float*)d_in[6];
    const float* ip_w      = (const float*)d_in[7];
    const float* ip_b      = (const float*)d_in[8];
    const float* s_inw     = (const float*)d_in[9];
    const float* s_convw   = (const float*)d_in[10];
    const float* s_convb   = (const float*)d_in[11];
    const float* s_xw      = (const float*)d_in[12];
    const float* s_dtw     = (const float*)d_in[13];
    const float* s_dtb     = (const float*)d_in[14];
    const float* s_alog    = (const float*)d_in[15];
    const float* s_d       = (const float*)d_in[16];
    const float* s_outw    = (const float*)d_in[17];
    const float* op_w      = (const float*)d_in[18];
    const float* op_b      = (const float*)d_in[19];
    const float* ln2_g     = (const float*)d_in[20];
    const float* ln2_b     = (const float*)d_in[21];
    const float* f_w1      = (const float*)d_in[22];
    const float* f_b1      = (const float*)d_in[23];
    const float* f_w2      = (const float*)d_in[24];
    const float* f_b2      = (const float*)d_in[25];
    const float* ln3_g     = (const float*)d_in[26];
    const float* ln3_b     = (const float*)d_in[27];

    float* base = nullptr;
    cudaGetSymbolAddress((void**)&base, g_buf);

    float* X    = base + OFF_X;
    float* LNb  = base + OFF_LN;
    float* B256 = base + OFF_B256;
    float* XZ   = base + OFF_XZ;
    float* XC   = base + OFF_XC;
    float* DBC  = base + OFF_DBC;
    float* DT   = base + OFF_DT;
    float* Y    = base + OFF_Y;
    float* FF   = base + OFF_FF;
    float* W2C  = base + OFF_W2C;
    float* WXZ  = base + OFF_WXZ;
    float* BXZ  = base + OFF_BXZ;

    const int M = (int)MTOK;
    const int CONV_BLOCKS = (int)(2 * MTOK * 64 / 256);
    const int LN_BLOCKS = (int)(MTOK / 8);

    // --- precompute composed weights -------------------------------------
    // W2C[l][g] = outw[l][g] @ opw[l][g-part]
    launch_tf64<0, false, false>(s_outw, op_w, nullptr, W2C,
                                 256, 256, 128, 24, 32768, 32768, 65536);
    // WXZ[l][g] = ipw[l][:, g*128:+128] @ inw[l][g]
    for (int g = 0; g < 2; g++) {
        launch_tf128<0, false>(ip_w + g * 128, s_inw + (long)g * 65536, nullptr,
                               WXZ + (long)g * 131072,
                               256, 512, 128, 256, 12,
                               65536, 131072, 262144, 0);
    }
    // BXZ[l][g] = ipb-slice @ inw[l][g]   (4 lanes per output)
    bxz_kernel<<<192, 256>>>(ip_b, s_inw, BXZ);

    // --- embedding + first LN1 -------------------------------------------
    embed_ln_kernel<<<M, 256>>>(input_ids, proj_w, proj_b, ln0_g, ln0_b, X);
    ln_kernel<<<LN_BLOCKS, 256>>>(X, nullptr, ln1_g, ln1_b, LNb);

    for (int l = 0; l < 12; l++) {
        // xz = LN1[rev_g] @ WXZ[l][g] + BXZ[l][g]   (ip composed in)
        launch_tf128<0, true>(LNb, WXZ + (long)l * 262144, BXZ + (long)l * 1024, XZ,
                              M, 512, 256, 256, 2,
                              0, 131072, MTOK * 512, 512);
        // conv + silu
        conv_silu_kernel<<<CONV_BLOCKS, 256>>>(XZ, s_convw + (long)l * 2 * 256 * 4,
                                               s_convb + (long)l * 2 * 256, XC);
        // dbc = xc @ xw (N=40 guarded) + fused dt
        launch_tf64<0, true, true>(XC, s_xw + (long)l * 2 * 256 * 40, nullptr, DBC,
                                   M, 40, 256, 2, MTOK * 256, 256 * 40, MTOK * 40,
                                   s_dtw + (long)l * 2 * 8 * 256,
                                   s_dtb + (long)l * 2 * 256, DT);
        // selective scan + fused silu(z) gate
        scan_kernel<<<256, 256>>>(DT, XC, DBC, XZ,
                                  s_alog + (long)l * 2 * 256 * 16,
                                  s_d + (long)l * 2 * 256, Y);
        // fused outw∘opw projection (+op_b) -> B256
        {
            dim3 grid(2, M / 64, 1);
            cudaFuncSetAttribute(outop_kernel,
                                 cudaFuncAttributeMaxDynamicSharedMemorySize, SMEM64);
            outop_kernel<<<grid, 256, SMEM64>>>(Y, W2C + (long)l * 2 * 65536,
                                                op_b + l * 256, B256);
        }
        // LN2 (residual)
        ln_kernel<<<LN_BLOCKS, 256>>>(B256, X, ln2_g + l * 256, ln2_b + l * 256, X);
        // ff = gelu(x @ w1 + b1)
        launch_tf128<2, false>(X, f_w1 + (long)l * 256 * 1024, f_b1 + l * 1024, FF,
                               M, 1024, 256, 256, 1, 0, 0, 0, 0);
        // f = ff @ w2 + b2
        launch_tf64<0, false, false>(FF, f_w2 + (long)l * 1024 * 256, f_b2 + l * 256,
                                     B256, M, 256, 1024, 1, 0, 0, 0);
        // LN3 fused with next layer's LN1
        float* dst = (l == 11) ? (float*)d_out : X;
        float* lnb = (l == 11) ? nullptr : LNb;
        const float* g1 = ln1_g + (l + 1 < 12 ? (l + 1) * 256 : 0);
        const float* b1 = ln1_b + (l + 1 < 12 ? (l + 1) * 256 : 0);
        ln3ln1_kernel<<<LN_BLOCKS, 256>>>(B256, X, ln3_g + l * 256, ln3_b + l * 256,
                                          g1, b1, dst, lnb);
    }
}

// round 16
// speedup vs baseline: 1.0468x; 1.0468x over previous
#include <cuda_runtime.h>
#include <math.h>
#include <stdint.h>

constexpr long MTOK  = 16 * 512;     // 8192 tokens

// ---------------------------------------------------------------------------
// Scratch arena
// ---------------------------------------------------------------------------
constexpr long OFF_X    = 0;
constexpr long OFF_LN   = OFF_X    + MTOK * 256;
constexpr long OFF_B256 = OFF_LN   + MTOK * 256;
constexpr long OFF_XZ   = OFF_B256 + MTOK * 256;
constexpr long OFF_XC   = OFF_XZ   + 2 * MTOK * 512;
constexpr long OFF_DBC  = OFF_XC   + 2 * MTOK * 256;
constexpr long OFF_DT   = OFF_DBC  + 2 * MTOK * 40;
constexpr long OFF_Y    = OFF_DT   + 2 * MTOK * 256;
constexpr long OFF_FF   = OFF_Y    + 2 * MTOK * 256;
constexpr long OFF_W2C  = OFF_FF   + MTOK * 1024;
constexpr long TOTAL_F  = OFF_W2C  + 24L * 256 * 256;

__device__ float g_buf[TOTAL_F];

__device__ __forceinline__ uint32_t smem_u32(const void* p)
{
    return (uint32_t)__cvta_generic_to_shared(p);
}

// ---------------------------------------------------------------------------
// Embedding: x = LN(ids @ proj_w + proj_b)  (runs once)
// ---------------------------------------------------------------------------
__global__ void embed_ln_kernel(const float* __restrict__ ids,
                                const float* __restrict__ pw,
                                const float* __restrict__ pb,
                                const float* __restrict__ gam,
                                const float* __restrict__ bet,
                                float* __restrict__ x)
{
    __shared__ float sin[32];
    __shared__ float sred[8];
    int m = blockIdx.x, d = threadIdx.x;
    if (d < 32) sin[d] = ids[(long)m * 32 + d];
    __syncthreads();
    float v = pb[d];
#pragma unroll
    for (int e = 0; e < 32; e++)
        v = fmaf(sin[e], pw[e * 256 + d], v);
    float s = v;
#pragma unroll
    for (int o = 16; o > 0; o >>= 1) s += __shfl_xor_sync(0xffffffffu, s, o);
    if ((d & 31) == 0) sred[d >> 5] = s;
    __syncthreads();
    float mean = 0.f;
#pragma unroll
    for (int i = 0; i < 8; i++) mean += sred[i];
    mean *= (1.f / 256.f);
    float c = v - mean;
    float q = c * c;
#pragma unroll
    for (int o = 16; o > 0; o >>= 1) q += __shfl_xor_sync(0xffffffffu, q, o);
    __syncthreads();
    if ((d & 31) == 0) sred[d >> 5] = q;
    __syncthreads();
    float var = 0.f;
#pragma unroll
    for (int i = 0; i < 8; i++) var += sred[i];
    var *= (1.f / 256.f);
    x[(long)m * 256 + d] = c * rsqrtf(var + 1e-5f) * gam[d] + bet[d];
}

// ---------------------------------------------------------------------------
// Warp-level LN helper on 8 registers
// ---------------------------------------------------------------------------
__device__ __forceinline__ void warp_ln8(float* a,
                                         const float* __restrict__ gam,
                                         const float* __restrict__ bet,
                                         int lane, float* o)
{
    float s = 0.f;
#pragma unroll
    for (int i = 0; i < 8; i++) s += a[i];
#pragma unroll
    for (int off = 16; off > 0; off >>= 1) s += __shfl_xor_sync(0xffffffffu, s, off);
    float mean = s * (1.f / 256.f);
    float q = 0.f;
#pragma unroll
    for (int i = 0; i < 8; i++) {
        float c = a[i] - mean;
        q = fmaf(c, c, q);
    }
#pragma unroll
    for (int off = 16; off > 0; off >>= 1) q += __shfl_xor_sync(0xffffffffu, q, off);
    float inv = rsqrtf(q * (1.f / 256.f) + 1e-5f);
    const float4* gp = (const float4*)(gam + lane * 8);
    const float4* bp = (const float4*)(bet + lane * 8);
    float4 g0 = gp[0], g1 = gp[1], b0 = bp[0], b1 = bp[1];
    o[0] = (a[0] - mean) * inv * g0.x + b0.x;
    o[1] = (a[1] - mean) * inv * g0.y + b0.y;
    o[2] = (a[2] - mean) * inv * g0.z + b0.z;
    o[3] = (a[3] - mean) * inv * g0.w + b0.w;
    o[4] = (a[4] - mean) * inv * g1.x + b1.x;
    o[5] = (a[5] - mean) * inv * g1.y + b1.y;
    o[6] = (a[6] - mean) * inv * g1.z + b1.z;
    o[7] = (a[7] - mean) * inv * g1.w + b1.w;
}

// ---------------------------------------------------------------------------
// Warp-per-token LayerNorm, optional residual.
// ---------------------------------------------------------------------------
__global__ void __launch_bounds__(256)
ln_kernel(const float* __restrict__ in,
          const float* __restrict__ res,
          const float* __restrict__ gam,
          const float* __restrict__ bet,
          float* __restrict__ out)
{
    int w = threadIdx.x >> 5, lane = threadIdx.x & 31;
    long m = (long)blockIdx.x * 8 + w;
    const float4* ip = (const float4*)(in + m * 256);
    float4 v0 = ip[lane * 2];
    float4 v1 = ip[lane * 2 + 1];
    if (res) {
        const float4* rp = (const float4*)(res + m * 256);
        float4 r0 = rp[lane * 2];
        float4 r1 = rp[lane * 2 + 1];
        v0.x += r0.x; v0.y += r0.y; v0.z += r0.z; v0.w += r0.w;
        v1.x += r1.x; v1.y += r1.y; v1.z += r1.z; v1.w += r1.w;
    }
    float a[8] = {v0.x, v0.y, v0.z, v0.w, v1.x, v1.y, v1.z, v1.w};
    float o[8];
    warp_ln8(a, gam, bet, lane, o);
    float4* op = (float4*)(out + m * 256);
    op[lane * 2]     = make_float4(o[0], o[1], o[2], o[3]);
    op[lane * 2 + 1] = make_float4(o[4], o[5], o[6], o[7]);
}

// ---------------------------------------------------------------------------
// Fused LN3 + LN1(next layer)
// ---------------------------------------------------------------------------
__global__ void __launch_bounds__(256)
ln3ln1_kernel(const float* __restrict__ in,
              const float* __restrict__ res,
              const float* __restrict__ g3,
              const float* __restrict__ b3,
              const float* __restrict__ g1,
              const float* __restrict__ b1,
              float* __restrict__ xout,
              float* __restrict__ lnb)
{
    int w = threadIdx.x >> 5, lane = threadIdx.x & 31;
    long m = (long)blockIdx.x * 8 + w;
    const float4* ip = (const float4*)(in + m * 256);
    const float4* rp = (const float4*)(res + m * 256);
    float4 v0 = ip[lane * 2], v1 = ip[lane * 2 + 1];
    float4 r0 = rp[lane * 2], r1 = rp[lane * 2 + 1];
    float a[8] = {v0.x + r0.x, v0.y + r0.y, v0.z + r0.z, v0.w + r0.w,
                  v1.x + r1.x, v1.y + r1.y, v1.z + r1.z, v1.w + r1.w};
    float o[8];
    warp_ln8(a, g3, b3, lane, o);
    float4* xp = (float4*)(xout + m * 256);
    xp[lane * 2]     = make_float4(o[0], o[1], o[2], o[3]);
    xp[lane * 2 + 1] = make_float4(o[4], o[5], o[6], o[7]);
    if (lnb) {
        float o2[8];
        warp_ln8(o, g1, b1, lane, o2);
        float4* lp = (float4*)(lnb + m * 256);
        lp[lane * 2]     = make_float4(o2[0], o2[1], o2[2], o2[3]);
        lp[lane * 2 + 1] = make_float4(o2[4], o2[5], o2[6], o2[7]);
    }
}

// ---------------------------------------------------------------------------
// TF32 GEMM, 256 threads, 128x128 tile, BK=32, 3-stage pipeline, 1 barrier.
// lda runtime. AREV: reverse A rows within each 512-token batch for g==1.
// ---------------------------------------------------------------------------
template<int ACT, bool AREV>
__global__ void __launch_bounds__(256, 2)
tf128_kernel(const float* __restrict__ A,
             const float* __restrict__ W,
             const float* __restrict__ bias,
             float* __restrict__ C,
             int M, int N, int K, int lda,
             long sAg, long sWg, long sCg)
{
    extern __shared__ uint32_t dyn[];
    constexpr int AW = 128 * 36;
    constexpr int SW = AW + 32 * 136;

    int g = blockIdx.z;
    A += (long)g * sAg;
    W += (long)g * sWg;
    C += (long)g * sCg;
    bool rev = AREV && (g == 1);

    int tid  = threadIdx.x;
    int warp = tid >> 5;
    int lane = tid & 31;
    int wm = (warp & 1) * 64;
    int wn = (warp >> 1) * 32;
    int gID = lane >> 2;
    int tig = lane & 3;
    int rowBase = blockIdx.y * 128;
    int colBase = blockIdx.x * 128;

    const float* Wbase = W + colBase;

    auto stage = [&](int buf, int k0) {
        uint32_t* As = dyn + buf * SW;
        uint32_t* Bs = dyn + buf * SW + AW;
#pragma unroll
        for (int it = 0; it < 4; it++) {
            int f = tid + it * 256;
            int r = f >> 3, k4 = (f & 7) * 4;
            int m = rowBase + r;
            if (rev) m = (m & ~511) + 511 - (m & 511);
            asm volatile("cp.async.ca.shared.global [%0], [%1], 16;\n"
                         :: "r"(smem_u32(&As[r * 36 + k4])),
                            "l"(A + (long)m * lda + k0 + k4));
        }
#pragma unroll
        for (int it = 0; it < 4; it++) {
            int f = tid + it * 256;
            int kr = f >> 5, n4 = (f & 31) * 4;
            asm volatile("cp.async.ca.shared.global [%0], [%1], 16;\n"
                         :: "r"(smem_u32(&Bs[kr * 136 + n4])),
                            "l"(Wbase + (long)(k0 + kr) * N + n4));
        }
        asm volatile("cp.async.commit_group;\n");
    };

    float acc[4][4][4];
#pragma unroll
    for (int a = 0; a < 4; a++)
#pragma unroll
        for (int b = 0; b < 4; b++)
#pragma unroll
            for (int c = 0; c < 4; c++) acc[a][b][c] = 0.f;

    auto compute = [&](int buf) {
        uint32_t* As = dyn + buf * SW;
        uint32_t* Bs = dyn + buf * SW + AW;
#pragma unroll
        for (int ks = 0; ks < 32; ks += 8) {
            uint32_t bf[4][2];
#pragma unroll
            for (int nt = 0; nt < 4; nt++) {
                int col = wn + nt * 8 + gID;
                bf[nt][0] = Bs[(ks + tig) * 136 + col];
                bf[nt][1] = Bs[(ks + tig + 4) * 136 + col];
            }
#pragma unroll
            for (int mt = 0; mt < 4; mt++) {
                int row = wm + mt * 16 + gID;
                uint32_t a0 = As[row * 36 + ks + tig] + 0x1000u;
                uint32_t a1 = As[(row + 8) * 36 + ks + tig] + 0x1000u;
                uint32_t a2 = As[row * 36 + ks + tig + 4] + 0x1000u;
                uint32_t a3 = As[(row + 8) * 36 + ks + tig + 4] + 0x1000u;
#pragma unroll
                for (int nt = 0; nt < 4; nt++) {
                    asm volatile(
                        "mma.sync.aligned.m16n8k8.row.col.f32.tf32.tf32.f32 "
                        "{%0,%1,%2,%3}, {%4,%5,%6,%7}, {%8,%9}, {%0,%1,%2,%3};\n"
                        : "+f"(acc[mt][nt][0]), "+f"(acc[mt][nt][1]),
                          "+f"(acc[mt][nt][2]), "+f"(acc[mt][nt][3])
                        : "r"(a0), "r"(a1), "r"(a2), "r"(a3),
                          "r"(bf[nt][0]), "r"(bf[nt][1]));
                }
            }
        }
    };

    int nk = K >> 5;
    stage(0, 0);
    if (nk > 1) stage(1, 32);
    for (int ki = 0; ki < nk; ki++) {
        if (ki < nk - 1) asm volatile("cp.async.wait_group 1;\n");
        else             asm volatile("cp.async.wait_group 0;\n");
        __syncthreads();
        int kn = ki + 2;
        if (kn < nk) stage(kn % 3, kn << 5);
        compute(ki % 3);
    }

#pragma unroll
    for (int mt = 0; mt < 4; mt++) {
        int row0 = rowBase + wm + mt * 16 + gID;
#pragma unroll
        for (int nt = 0; nt < 4; nt++) {
            int col = colBase + wn + nt * 8 + tig * 2;
            float b0 = 0.f, b1 = 0.f;
            if (bias) { b0 = bias[col]; b1 = bias[col + 1]; }
            float v[4];
            v[0] = acc[mt][nt][0] + b0;
            v[1] = acc[mt][nt][1] + b1;
            v[2] = acc[mt][nt][2] + b0;
            v[3] = acc[mt][nt][3] + b1;
            if (ACT == 2) {
#pragma unroll
                for (int q = 0; q < 4; q++)
                    v[q] = 0.5f * v[q] * (1.f + erff(v[q] * 0.70710678118654752f));
            }
            *(float2*)&C[(long)row0 * N + col] = make_float2(v[0], v[1]);
            *(float2*)&C[(long)(row0 + 8) * N + col] = make_float2(v[2], v[3]);
        }
    }
}

// ---------------------------------------------------------------------------
// TF32 GEMM, 256 threads, 64x128 tile (plain store; dbc+dt fusion)
// ---------------------------------------------------------------------------
template<int ACT, bool NG, bool DTF>
__global__ void __launch_bounds__(256, 2)
tf64_kernel(const float* __restrict__ A,
            const float* __restrict__ W,
            const float* __restrict__ bias,
            float* __restrict__ C,
            int M, int N, int K,
            long sAg, long sWg, long sCg,
            const float* __restrict__ dtw,
            const float* __restrict__ dtb,
            float* __restrict__ DTout)
{
    extern __shared__ uint32_t dyn[];
    constexpr int AW = 64 * 36;
    constexpr int SW = AW + 32 * 136;

    int g = blockIdx.z;
    A += (long)g * sAg;
    W += (long)g * sWg;
    C += (long)g * sCg;
    if (DTF) {
        dtw += (long)g * 2048;
        dtb += (long)g * 256;
        DTout += (long)g * MTOK * 256;
    }

    int tid  = threadIdx.x;
    int warp = tid >> 5;
    int lane = tid & 31;
    int wm = (warp & 1) * 32;
    int wn = (warp >> 1) * 32;
    int gID = lane >> 2;
    int tig = lane & 3;
    int rowBase = blockIdx.y * 64;
    int colBase = blockIdx.x * 128;

    const float* Abase = A + (long)rowBase * K;
    const float* Wbase = W + colBase;

    if (NG) {
#pragma unroll
        for (int s = 0; s < 3; s++) {
            uint32_t* Bs = dyn + s * SW + AW;
            for (int f = tid; f < 1024; f += 256) {
                int kr = f >> 5, n4 = (f & 31) * 4;
                if (n4 + 4 > N)
                    *(uint4*)&Bs[kr * 136 + n4] = make_uint4(0, 0, 0, 0);
            }
        }
        __syncthreads();
    }

    auto stage = [&](int buf, int k0) {
        uint32_t* As = dyn + buf * SW;
        uint32_t* Bs = dyn + buf * SW + AW;
#pragma unroll
        for (int it = 0; it < 2; it++) {
            int f = tid + it * 256;
            int r = f >> 3, k4 = (f & 7) * 4;
            asm volatile("cp.async.ca.shared.global [%0], [%1], 16;\n"
                         :: "r"(smem_u32(&As[r * 36 + k4])),
                            "l"(Abase + (long)r * K + k0 + k4));
        }
#pragma unroll
        for (int it = 0; it < 4; it++) {
            int f = tid + it * 256;
            int kr = f >> 5, n4 = (f & 31) * 4;
            if (!NG || n4 + 4 <= N)
                asm volatile("cp.async.ca.shared.global [%0], [%1], 16;\n"
                             :: "r"(smem_u32(&Bs[kr * 136 + n4])),
                                "l"(Wbase + (long)(k0 + kr) * N + n4));
        }
        asm volatile("cp.async.commit_group;\n");
    };

    float acc[2][4][4];
#pragma unroll
    for (int a = 0; a < 2; a++)
#pragma unroll
        for (int b = 0; b < 4; b++)
#pragma unroll
            for (int c = 0; c < 4; c++) acc[a][b][c] = 0.f;

    auto compute = [&](int buf) {
        uint32_t* As = dyn + buf * SW;
        uint32_t* Bs = dyn + buf * SW + AW;
#pragma unroll
        for (int ks = 0; ks < 32; ks += 8) {
            uint32_t bf[4][2];
#pragma unroll
            for (int nt = 0; nt < 4; nt++) {
                int col = wn + nt * 8 + gID;
                bf[nt][0] = Bs[(ks + tig) * 136 + col];
                bf[nt][1] = Bs[(ks + tig + 4) * 136 + col];
            }
#pragma unroll
            for (int mt = 0; mt < 2; mt++) {
                int row = wm + mt * 16 + gID;
                uint32_t a0 = As[row * 36 + ks + tig] + 0x1000u;
                uint32_t a1 = As[(row + 8) * 36 + ks + tig] + 0x1000u;
                uint32_t a2 = As[row * 36 + ks + tig + 4] + 0x1000u;
                uint32_t a3 = As[(row + 8) * 36 + ks + tig + 4] + 0x1000u;
#pragma unroll
                for (int nt = 0; nt < 4; nt++) {
                    asm volatile(
                        "mma.sync.aligned.m16n8k8.row.col.f32.tf32.tf32.f32 "
                        "{%0,%1,%2,%3}, {%4,%5,%6,%7}, {%8,%9}, {%0,%1,%2,%3};\n"
                        : "+f"(acc[mt][nt][0]), "+f"(acc[mt][nt][1]),
                          "+f"(acc[mt][nt][2]), "+f"(acc[mt][nt][3])
                        : "r"(a0), "r"(a1), "r"(a2), "r"(a3),
                          "r"(bf[nt][0]), "r"(bf[nt][1]));
                }
            }
        }
    };

    int nk = K >> 5;
    stage(0, 0);
    if (nk > 1) stage(1, 32);
    for (int ki = 0; ki < nk; ki++) {
        if (ki < nk - 1) asm volatile("cp.async.wait_group 1;\n");
        else             asm volatile("cp.async.wait_group 0;\n");
        __syncthreads();
        int kn = ki + 2;
        if (kn < nk) stage(kn % 3, kn << 5);
        compute(ki % 3);
    }

#pragma unroll
    for (int mt = 0; mt < 2; mt++) {
        int row0 = rowBase + wm + mt * 16 + gID;
#pragma unroll
        for (int nt = 0; nt < 4; nt++) {
            int col = colBase + wn + nt * 8 + tig * 2;
            if (NG && col >= N) continue;
            float b0 = 0.f, b1 = 0.f;
            if (bias) { b0 = bias[col]; b1 = bias[col + 1]; }
            float v[4];
            v[0] = acc[mt][nt][0] + b0;
            v[1] = acc[mt][nt][1] + b1;
            v[2] = acc[mt][nt][2] + b0;
            v[3] = acc[mt][nt][3] + b1;
            if (ACT == 2) {
#pragma unroll
                for (int q = 0; q < 4; q++)
                    v[q] = 0.5f * v[q] * (1.f + erff(v[q] * 0.70710678118654752f));
            }
            *(float2*)&C[(long)row0 * N + col] = make_float2(v[0], v[1]);
            *(float2*)&C[(long)(row0 + 8) * N + col] = make_float2(v[2], v[3]);
        }
    }

    if (DTF) {
        float* dbs = (float*)(dyn + 3 * SW);
        if (warp < 2) {
            int col = tig * 2;
#pragma unroll
            for (int mt = 0; mt < 2; mt++) {
#pragma unroll
                for (int h = 0; h < 2; h++) {
                    int rl = wm + mt * 16 + gID + h * 8;
                    dbs[rl * 8 + col]     = acc[mt][0][h * 2];
                    dbs[rl * 8 + col + 1] = acc[mt][0][h * 2 + 1];
                }
            }
        }
        __syncthreads();
        int d = tid;
        float wreg[8];
#pragma unroll
        for (int r = 0; r < 8; r++) wreg[r] = dtw[r * 256 + d];
        float bb = dtb[d];
        float* dto = DTout + (long)rowBase * 256 + d;
        for (int r = 0; r < 64; r++) {
            float s = bb;
#pragma unroll
            for (int j = 0; j < 8; j++) s = fmaf(dbs[r * 8 + j], wreg[j], s);
            s = (s > 20.f) ? s : log1pf(expf(s));
            dto[(long)r * 256] = s;
        }
    }
}

// ---------------------------------------------------------------------------
// Fused out-projection: C = y0 @ Wc[0] + y1[rev] @ Wc[1] + bias  ([M,256])
// Wc: composed [2][256][256]. 64x128 tile, 16 K-slabs (2 groups x 8).
// ---------------------------------------------------------------------------
__global__ void __launch_bounds__(256, 2)
outop_kernel(const float* __restrict__ Y,
             const float* __restrict__ Wc,
             const float* __restrict__ bias,
             float* __restrict__ C)
{
    extern __shared__ uint32_t dyn[];
    constexpr int AW = 64 * 36;
    constexpr int SW = AW + 32 * 136;
    constexpr int N = 256;

    int tid  = threadIdx.x;
    int warp = tid >> 5;
    int lane = tid & 31;
    int wm = (warp & 1) * 32;
    int wn = (warp >> 1) * 32;
    int gID = lane >> 2;
    int tig = lane & 3;
    int rowBase = blockIdx.y * 64;
    int colBase = blockIdx.x * 128;

    auto stage = [&](int buf, int s) {
        int g = s >> 3;
        int k0 = (s & 7) << 5;
        const float* Ab = Y + (long)g * MTOK * 256;
        const float* Wb = Wc + (long)g * 65536 + colBase;
        uint32_t* As = dyn + buf * SW;
        uint32_t* Bs = dyn + buf * SW + AW;
#pragma unroll
        for (int it = 0; it < 2; it++) {
            int f = tid + it * 256;
            int r = f >> 3, k4 = (f & 7) * 4;
            int m = rowBase + r;
            if (g) m = (m & ~511) + 511 - (m & 511);
            asm volatile("cp.async.ca.shared.global [%0], [%1], 16;\n"
                         :: "r"(smem_u32(&As[r * 36 + k4])),
                            "l"(Ab + (long)m * 256 + k0 + k4));
        }
#pragma unroll
        for (int it = 0; it < 4; it++) {
            int f = tid + it * 256;
            int kr = f >> 5, n4 = (f & 31) * 4;
            asm volatile("cp.async.ca.shared.global [%0], [%1], 16;\n"
                         :: "r"(smem_u32(&Bs[kr * 136 + n4])),
                            "l"(Wb + (long)(k0 + kr) * N + n4));
        }
        asm volatile("cp.async.commit_group;\n");
    };

    float acc[2][4][4];
#pragma unroll
    for (int a = 0; a < 2; a++)
#pragma unroll
        for (int b = 0; b < 4; b++)
#pragma unroll
            for (int c = 0; c < 4; c++) acc[a][b][c] = 0.f;

    auto compute = [&](int buf) {
        uint32_t* As = dyn + buf * SW;
        uint32_t* Bs = dyn + buf * SW + AW;
#pragma unroll
        for (int ks = 0; ks < 32; ks += 8) {
            uint32_t bf[4][2];
#pragma unroll
            for (int nt = 0; nt < 4; nt++) {
                int col = wn + nt * 8 + gID;
                bf[nt][0] = Bs[(ks + tig) * 136 + col];
                bf[nt][1] = Bs[(ks + tig + 4) * 136 + col];
            }
#pragma unroll
            for (int mt = 0; mt < 2; mt++) {
                int row = wm + mt * 16 + gID;
                uint32_t a0 = As[row * 36 + ks + tig] + 0x1000u;
                uint32_t a1 = As[(row + 8) * 36 + ks + tig] + 0x1000u;
                uint32_t a2 = As[row * 36 + ks + tig + 4] + 0x1000u;
                uint32_t a3 = As[(row + 8) * 36 + ks + tig + 4] + 0x1000u;
#pragma unroll
                for (int nt = 0; nt < 4; nt++) {
                    asm volatile(
                        "mma.sync.aligned.m16n8k8.row.col.f32.tf32.tf32.f32 "
                        "{%0,%1,%2,%3}, {%4,%5,%6,%7}, {%8,%9}, {%0,%1,%2,%3};\n"
                        : "+f"(acc[mt][nt][0]), "+f"(acc[mt][nt][1]),
                          "+f"(acc[mt][nt][2]), "+f"(acc[mt][nt][3])
                        : "r"(a0), "r"(a1), "r"(a2), "r"(a3),
                          "r"(bf[nt][0]), "r"(bf[nt][1]));
                }
            }
        }
    };

    stage(0, 0);
    stage(1, 1);
    for (int s = 0; s < 16; s++) {
        if (s < 15) asm volatile("cp.async.wait_group 1;\n");
        else        asm volatile("cp.async.wait_group 0;\n");
        __syncthreads();
        int sn = s + 2;
        if (sn < 16) stage(sn % 3, sn);
        compute(s % 3);
    }

#pragma unroll
    for (int mt = 0; mt < 2; mt++) {
        int row0 = rowBase + wm + mt * 16 + gID;
#pragma unroll
        for (int nt = 0; nt < 4; nt++) {
            int col = colBase + wn + nt * 8 + tig * 2;
            float b0 = bias[col], b1 = bias[col + 1];
            *(float2*)&C[(long)row0 * N + col] =
                make_float2(acc[mt][nt][0] + b0, acc[mt][nt][1] + b1);
            *(float2*)&C[(long)(row0 + 8) * N + col] =
                make_float2(acc[mt][nt][2] + b0, acc[mt][nt][3] + b1);
        }
    }
}

// ---------------------------------------------------------------------------
// depthwise causal conv (K=4) + bias + silu; 4 t-outputs per thread
// ---------------------------------------------------------------------------
__global__ void conv_silu_kernel(const float* __restrict__ xz,
                                 const float* __restrict__ convw,
                                 const float* __restrict__ convb,
                                 float* __restrict__ xc)
{
    long i = (long)blockIdx.x * 256 + threadIdx.x;
    if (i >= 2 * MTOK * 64) return;
    int d = (int)(i & 255);
    long q = i >> 8;
    int t0 = (int)(q & 127) * 4;
    int b  = (int)((q >> 7) & 15);
    int g  = (int)(q >> 11);

    const float4 w4 = *(const float4*)(convw + ((long)g * 256 + d) * 4);
    float bias = convb[(long)g * 256 + d];

    long mrow = (long)g * MTOK + (long)b * 512 + t0;
    const float* xp = xz + mrow * 512 + d;
    float xv[7];
#pragma unroll
    for (int j = 0; j < 7; j++) {
        int t = t0 - 3 + j;
        xv[j] = (t >= 0) ? xp[(long)(j - 3) * 512] : 0.f;
    }
    float* op = xc + mrow * 256 + d;
#pragma unroll
    for (int j = 0; j < 4; j++) {
        float acc = bias;
        acc = fmaf(xv[j],     w4.x, acc);
        acc = fmaf(xv[j + 1], w4.y, acc);
        acc = fmaf(xv[j + 2], w4.z, acc);
        acc = fmaf(xv[j + 3], w4.w, acc);
        op[(long)j * 256] = acc / (1.f + __expf(-acc));
    }
}

// ---------------------------------------------------------------------------
// Selective scan, 4 lanes per (g,b,d) group, 4 states per lane (float4 B/C),
// fully software-pipelined + fused silu(z) gate.
// grid: 8192 groups * 4 lanes / 128 threads = 256 blocks.
// ---------------------------------------------------------------------------
__global__ void __launch_bounds__(128)
scan_kernel(const float* __restrict__ dt,
            const float* __restrict__ xc,
            const float* __restrict__ dbc,
            const float* __restrict__ xz,
            const float* __restrict__ alog,
            const float* __restrict__ dpar,
            float* __restrict__ y)
{
    int gidx = blockIdx.x * 32 + (threadIdx.x >> 2);   // group 0..8191
    int li = threadIdx.x & 3;                          // lane in group
    int g = gidx >> 12;
    int b = (gidx >> 8) & 15;
    int d = gidx & 255;

    const float4 al = *(const float4*)&alog[((long)(g * 256 + d)) * 16 + li * 4];
    const float L2E = 1.4426950408889634f;
    float A0 = -__expf(al.x) * L2E;
    float A1 = -__expf(al.y) * L2E;
    float A2 = -__expf(al.z) * L2E;
    float A3 = -__expf(al.w) * L2E;
    float dp = dpar[(long)g * 256 + d];

    long mbase = (long)g * MTOK + (long)b * 512;
    const float* dtp = dt + mbase * 256 + d;
    const float* xcp = xc + mbase * 256 + d;
    const float* dbp = dbc + mbase * 40;
    const float* zp  = xz + mbase * 512 + 256 + d;
    float* yp = y + mbase * 256 + d;

    float h0 = 0.f, h1 = 0.f, h2 = 0.f, h3 = 0.f;

    float dtv_n = dtp[0];
    float xv_n  = xcp[0];
    float z_n   = zp[0];
    float4 B_n  = *(const float4*)&dbp[8 + li * 4];
    float4 C_n  = *(const float4*)&dbp[24 + li * 4];

    for (int t = 0; t < 512; t++) {
        float dtv = dtv_n, xv = xv_n, z = z_n;
        float4 Bv = B_n, Cv = C_n;
        long tn = (t + 1 < 512) ? t + 1 : 511;
        dtv_n = dtp[tn * 256];
        xv_n  = xcp[tn * 256];
        z_n   = zp[tn * 512];
        B_n   = *(const float4*)&dbp[tn * 40 + 8 + li * 4];
        C_n   = *(const float4*)&dbp[tn * 40 + 24 + li * 4];

        float dx = dtv * xv;
        h0 = exp2f(dtv * A0) * h0 + dx * Bv.x;
        h1 = exp2f(dtv * A1) * h1 + dx * Bv.y;
        h2 = exp2f(dtv * A2) * h2 + dx * Bv.z;
        h3 = exp2f(dtv * A3) * h3 + dx * Bv.w;
        float p = h0 * Cv.x + h1 * Cv.y + h2 * Cv.z + h3 * Cv.w;
        p += __shfl_xor_sync(0xffffffffu, p, 2);
        p += __shfl_xor_sync(0xffffffffu, p, 1);
        if (li == 0) {
            float sz = z / (1.f + __expf(-z));
            yp[(long)t * 256] = (p + dp * xv) * sz;
        }
    }
}

// ---------------------------------------------------------------------------
// Launch helpers
// ---------------------------------------------------------------------------
constexpr int SMEM128 = 3 * (128 * 36 + 32 * 136) * 4;
constexpr int SMEM64  = 3 * (64 * 36 + 32 * 136) * 4 + 2048;

template<int ACT, bool AREV>
static void launch_tf128(const float* A, const float* W, const float* bias, float* C,
                         int M, int N, int K, int lda, int G,
                         long sAg, long sWg, long sCg)
{
    cudaFuncSetAttribute(tf128_kernel<ACT, AREV>,
                         cudaFuncAttributeMaxDynamicSharedMemorySize, SMEM128);
    dim3 grid(N / 128, M / 128, G);
    tf128_kernel<ACT, AREV><<<grid, 256, SMEM128>>>(A, W, bias, C, M, N, K, lda,
                                                    sAg, sWg, sCg);
}

template<int ACT, bool NG, bool DTF>
static void launch_tf64(const float* A, const float* W, const float* bias, float* C,
                        int M, int N, int K, int G,
                        long sAg, long sWg, long sCg,
                        const float* dtw = nullptr, const float* dtb = nullptr,
                        float* DTout = nullptr)
{
    cudaFuncSetAttribute(tf64_kernel<ACT, NG, DTF>,
                         cudaFuncAttributeMaxDynamicSharedMemorySize, SMEM64);
    dim3 grid((N + 127) / 128, M / 64, G);
    tf64_kernel<ACT, NG, DTF><<<grid, 256, SMEM64>>>(
        A, W, bias, C, M, N, K, sAg, sWg, sCg, dtw, dtb, DTout);
}

extern "C" void kernel_launch(void* const* d_in, const int* in_sizes, int n_in,
                              void* d_out, int out_size)
{
    const float* input_ids = (const float*)d_in[0];
    const float* proj_w    = (const float*)d_in[1];
    const float* proj_b    = (const float*)d_in[2];
    const float* ln0_g     = (const float*)d_in[3];
    const float* ln0_b     = (const float*)d_in[4];
    const float* ln1_g     = (const float*)d_in[5];
    const float* ln1_b     = (const float*)d_in[6];
    const float* ip_w      = (const float*)d_in[7];
    const float* ip_b      = (const float*)d_in[8];
    const float* s_inw     = (const float*)d_in[9];
    const float* s_convw   = (const float*)d_in[10];
    const float* s_convb   = (const float*)d_in[11];
    const float* s_xw      = (const float*)d_in[12];
    const float* s_dtw     = (const float*)d_in[13];
    const float* s_dtb     = (const float*)d_in[14];
    const float* s_alog    = (const float*)d_in[15];
    const float* s_d       = (const float*)d_in[16];
    const float* s_outw    = (const float*)d_in[17];
    const float* op_w      = (const float*)d_in[18];
    const float* op_b      = (const float*)d_in[19];
    const float* ln2_g     = (const float*)d_in[20];
    const float* ln2_b     = (const float*)d_in[21];
    const float* f_w1      = (const float*)d_in[22];
    const float* f_b1      = (const float*)d_in[23];
    const float* f_w2      = (const float*)d_in[24];
    const float* f_b2      = (const float*)d_in[25];
    const float* ln3_g     = (const float*)d_in[26];
    const float* ln3_b     = (const float*)d_in[27];

    float* base = nullptr;
    cudaGetSymbolAddress((void**)&base, g_buf);

    float* X    = base + OFF_X;
    float* LNb  = base + OFF_LN;
    float* B256 = base + OFF_B256;
    float* XZ   = base + OFF_XZ;
    float* XC   = base + OFF_XC;
    float* DBC  = base + OFF_DBC;
    float* DT   = base + OFF_DT;
    float* Y    = base + OFF_Y;
    float* FF   = base + OFF_FF;
    float* W2C  = base + OFF_W2C;

    const int M = (int)MTOK;
    const int CONV_BLOCKS = (int)(2 * MTOK * 64 / 256);
    const int LN_BLOCKS = (int)(MTOK / 8);

    // --- precompute composed out-proj weights -----------------------------
    // W2C[l][g] = outw[l][g] @ opw[l][g-part]   (24 batched 256x128 @ 128x256)
    launch_tf64<0, false, false>(s_outw, op_w, nullptr, W2C,
                                 256, 256, 128, 24, 32768, 32768, 65536);

    // --- embedding + first LN1 -------------------------------------------
    embed_ln_kernel<<<M, 256>>>(input_ids, proj_w, proj_b, ln0_g, ln0_b, X);
    ln_kernel<<<LN_BLOCKS, 256>>>(X, nullptr, ln1_g, ln1_b, LNb);

    for (int l = 0; l < 12; l++) {
        // in-proj h = LN1 @ ip_w + ip_b -> B256
        launch_tf64<0, false, false>(LNb, ip_w + (long)l * 256 * 256, ip_b + l * 256,
                                     B256, M, 256, 256, 1, 0, 0, 0);
        // xz = h-slice @ inw (group col offset + row reversal for g=1)
        launch_tf128<0, true>(B256, s_inw + (long)l * 2 * 128 * 512, nullptr, XZ,
                              M, 512, 128, 256, 2, 128, 128 * 512, MTOK * 512);
        // conv + silu
        conv_silu_kernel<<<CONV_BLOCKS, 256>>>(XZ, s_convw + (long)l * 2 * 256 * 4,
                                               s_convb + (long)l * 2 * 256, XC);
        // dbc = xc @ xw (N=40 guarded) + fused dt
        launch_tf64<0, true, true>(XC, s_xw + (long)l * 2 * 256 * 40, nullptr, DBC,
                                   M, 40, 256, 2, MTOK * 256, 256 * 40, MTOK * 40,
                                   s_dtw + (long)l * 2 * 8 * 256,
                                   s_dtb + (long)l * 2 * 256, DT);
        // selective scan + fused silu(z) gate (4-lane groups, float4 B/C)
        scan_kernel<<<256, 128>>>(DT, XC, DBC, XZ,
                                  s_alog + (long)l * 2 * 256 * 16,
                                  s_d + (long)l * 2 * 256, Y);
        // fused outw∘opw projection (+op_b) -> B256
        {
            dim3 grid(2, M / 64, 1);
            cudaFuncSetAttribute(outop_kernel,
                                 cudaFuncAttributeMaxDynamicSharedMemorySize, SMEM64);
            outop_kernel<<<grid, 256, SMEM64>>>(Y, W2C + (long)l * 2 * 65536,
                                                op_b + l * 256, B256);
        }
        // LN2 (residual)
        ln_kernel<<<LN_BLOCKS, 256>>>(B256, X, ln2_g + l * 256, ln2_b + l * 256, X);
        // ff = gelu(x @ w1 + b1)
        launch_tf128<2, false>(X, f_w1 + (long)l * 256 * 1024, f_b1 + l * 1024, FF,
                               M, 1024, 256, 256, 1, 0, 0, 0);
        // f = ff @ w2 + b2
        launch_tf64<0, false, false>(FF, f_w2 + (long)l * 1024 * 256, f_b2 + l * 256,
                                     B256, M, 256, 1024, 1, 0, 0, 0);
        // LN3 fused with next layer's LN1
        float* dst = (l == 11) ? (float*)d_out : X;
        float* lnb = (l == 11) ? nullptr : LNb;
        const float* g1 = ln1_g + (l + 1 < 12 ? (l + 1) * 256 : 0);
        const float* b1 = ln1_b + (l + 1 < 12 ? (l + 1) * 256 : 0);
        ln3ln1_kernel<<<LN_BLOCKS, 256>>>(B256, X, ln3_g + l * 256, ln3_b + l * 256,
                                          g1, b1, dst, lnb);
    }
}

// round 17
// speedup vs baseline: 1.2601x; 1.2038x over previous
#include <cuda_runtime.h>
#include <cuda_fp16.h>
#include <math.h>
#include <stdint.h>

constexpr long MTOK = 16 * 512;      // 8192 tokens
constexpr long MT256 = MTOK * 256;

// ---------------------------------------------------------------------------
// Scratch arena (float units; half region aliased at OFF_HALF)
// ---------------------------------------------------------------------------
constexpr long OFF_X    = 0;                          // f32 [M,256]
constexpr long OFF_B256 = OFF_X    + MT256;           // f32 [M,256]
constexpr long OFF_DBC  = OFF_B256 + MT256;           // f32 [2,M,40]
constexpr long OFF_DT   = OFF_DBC  + 2 * MTOK * 40;   // f32 [2,M,256]
constexpr long OFF_W2C  = OFF_DT   + 2 * MT256;       // f32 [24,256,256]
constexpr long OFF_HALF = OFF_W2C  + 24L * 65536;
// half offsets (half units, relative to half base)
constexpr long HLNB  = 0;                    // [M,256]
constexpr long HHB   = HLNB  + MT256;        // [M,256]
constexpr long HXZ   = HHB   + MT256;        // [2,M,512]
constexpr long HXC   = HXZ   + 2 * MTOK * 512; // [2,M,256]
constexpr long HY    = HXC   + 2 * MT256;    // [2,M,256]
constexpr long HXH   = HY    + 2 * MT256;    // [M,256]
constexpr long HFF   = HXH   + MT256;        // [M,1024]
constexpr long HIPWT = HFF   + MTOK * 1024;  // [12,256,256]
constexpr long HINWT = HIPWT + 12L * 65536;  // [24,512,128]
constexpr long HXWT  = HINWT + 24L * 65536;  // [24,40,256]
constexpr long HW1T  = HXWT  + 24L * 10240;  // [12,1024,256]
constexpr long HW2T  = HW1T  + 12L * 262144; // [12,256,1024]
constexpr long HOPWT = HW2T  + 12L * 262144; // [24,256,128]
constexpr long HOUTW = HOPWT + 24L * 32768;  // [24,256,128] row-major
constexpr long HW2CT = HOUTW + 24L * 32768;  // [24,256,256]
constexpr long HALF_TOT = HW2CT + 24L * 65536;
constexpr long TOTAL_F = OFF_HALF + (HALF_TOT + 1) / 2;

__device__ float g_buf[TOTAL_F];

__device__ __forceinline__ uint32_t smem_u32(const void* p)
{
    return (uint32_t)__cvta_generic_to_shared(p);
}

__device__ __forceinline__ uint32_t h2u(float a, float b)
{
    __half2 h = __floats2half2_rn(a, b);
    return *(uint32_t*)&h;
}

// ---------------------------------------------------------------------------
// Weight convert (row-major fp32 -> fp16)
// ---------------------------------------------------------------------------
__global__ void cvt_kernel(const float* __restrict__ in, __half* __restrict__ out,
                           long n)
{
    long i = (long)blockIdx.x * 256 + threadIdx.x;
    if (i < n) out[i] = __float2half(in[i]);
}

// ---------------------------------------------------------------------------
// Transpose + convert: in fp32 [R][C] -> out fp16 [C][R]  (batched)
// ---------------------------------------------------------------------------
__global__ void transcvt_kernel(const float* __restrict__ in,
                                __half* __restrict__ out,
                                int R, int C, long sIn, long sOut)
{
    __shared__ float tile[32][33];
    in  += (long)blockIdx.z * sIn;
    out += (long)blockIdx.z * sOut;
    int c0 = blockIdx.x * 32, r0 = blockIdx.y * 32;
    int tx = threadIdx.x, ty = threadIdx.y;
#pragma unroll
    for (int j = 0; j < 32; j += 8) {
        int r = r0 + ty + j, c = c0 + tx;
        tile[ty + j][tx] = (r < R && c < C) ? in[(long)r * C + c] : 0.f;
    }
    __syncthreads();
#pragma unroll
    for (int j = 0; j < 32; j += 8) {
        int c = c0 + ty + j, r = r0 + tx;
        if (c < C && r < R) out[(long)c * R + r] = __float2half(tile[tx][ty + j]);
    }
}

// ---------------------------------------------------------------------------
// Embedding: x = LN(ids @ proj_w + proj_b)
// ---------------------------------------------------------------------------
__global__ void embed_ln_kernel(const float* __restrict__ ids,
                                const float* __restrict__ pw,
                                const float* __restrict__ pb,
                                const float* __restrict__ gam,
                                const float* __restrict__ bet,
                                float* __restrict__ x)
{
    __shared__ float sin[32];
    __shared__ float sred[8];
    int m = blockIdx.x, d = threadIdx.x;
    if (d < 32) sin[d] = ids[(long)m * 32 + d];
    __syncthreads();
    float v = pb[d];
#pragma unroll
    for (int e = 0; e < 32; e++)
        v = fmaf(sin[e], pw[e * 256 + d], v);
    float s = v;
#pragma unroll
    for (int o = 16; o > 0; o >>= 1) s += __shfl_xor_sync(0xffffffffu, s, o);
    if ((d & 31) == 0) sred[d >> 5] = s;
    __syncthreads();
    float mean = 0.f;
#pragma unroll
    for (int i = 0; i < 8; i++) mean += sred[i];
    mean *= (1.f / 256.f);
    float c = v - mean;
    float q = c * c;
#pragma unroll
    for (int o = 16; o > 0; o >>= 1) q += __shfl_xor_sync(0xffffffffu, q, o);
    __syncthreads();
    if ((d & 31) == 0) sred[d >> 5] = q;
    __syncthreads();
    float var = 0.f;
#pragma unroll
    for (int i = 0; i < 8; i++) var += sred[i];
    var *= (1.f / 256.f);
    x[(long)m * 256 + d] = c * rsqrtf(var + 1e-5f) * gam[d] + bet[d];
}

// ---------------------------------------------------------------------------
// Warp-level LN helper on 8 registers
// ---------------------------------------------------------------------------
__device__ __forceinline__ void warp_ln8(float* a,
                                         const float* __restrict__ gam,
                                         const float* __restrict__ bet,
                                         int lane, float* o)
{
    float s = 0.f;
#pragma unroll
    for (int i = 0; i < 8; i++) s += a[i];
#pragma unroll
    for (int off = 16; off > 0; off >>= 1) s += __shfl_xor_sync(0xffffffffu, s, off);
    float mean = s * (1.f / 256.f);
    float q = 0.f;
#pragma unroll
    for (int i = 0; i < 8; i++) {
        float c = a[i] - mean;
        q = fmaf(c, c, q);
    }
#pragma unroll
    for (int off = 16; off > 0; off >>= 1) q += __shfl_xor_sync(0xffffffffu, q, off);
    float inv = rsqrtf(q * (1.f / 256.f) + 1e-5f);
    const float4* gp = (const float4*)(gam + lane * 8);
    const float4* bp = (const float4*)(bet + lane * 8);
    float4 g0 = gp[0], g1 = gp[1], b0 = bp[0], b1 = bp[1];
    o[0] = (a[0] - mean) * inv * g0.x + b0.x;
    o[1] = (a[1] - mean) * inv * g0.y + b0.y;
    o[2] = (a[2] - mean) * inv * g0.z + b0.z;
    o[3] = (a[3] - mean) * inv * g0.w + b0.w;
    o[4] = (a[4] - mean) * inv * g1.x + b1.x;
    o[5] = (a[5] - mean) * inv * g1.y + b1.y;
    o[6] = (a[6] - mean) * inv * g1.z + b1.z;
    o[7] = (a[7] - mean) * inv * g1.w + b1.w;
}

__device__ __forceinline__ void store_h8(__half* p, const float* o)
{
    uint4 u;
    u.x = h2u(o[0], o[1]);
    u.y = h2u(o[2], o[3]);
    u.z = h2u(o[4], o[5]);
    u.w = h2u(o[6], o[7]);
    *(uint4*)p = u;
}

// ---------------------------------------------------------------------------
// Warp-per-token LayerNorm; optional residual; outputs f32 and/or f16
// ---------------------------------------------------------------------------
__global__ void __launch_bounds__(256)
ln_kernel(const float* __restrict__ in,
          const float* __restrict__ res,
          const float* __restrict__ gam,
          const float* __restrict__ bet,
          float* __restrict__ outf,
          __half* __restrict__ outh)
{
    int w = threadIdx.x >> 5, lane = threadIdx.x & 31;
    long m = (long)blockIdx.x * 8 + w;
    const float4* ip = (const float4*)(in + m * 256);
    float4 v0 = ip[lane * 2];
    float4 v1 = ip[lane * 2 + 1];
    if (res) {
        const float4* rp = (const float4*)(res + m * 256);
        float4 r0 = rp[lane * 2];
        float4 r1 = rp[lane * 2 + 1];
        v0.x += r0.x; v0.y += r0.y; v0.z += r0.z; v0.w += r0.w;
        v1.x += r1.x; v1.y += r1.y; v1.z += r1.z; v1.w += r1.w;
    }
    float a[8] = {v0.x, v0.y, v0.z, v0.w, v1.x, v1.y, v1.z, v1.w};
    float o[8];
    warp_ln8(a, gam, bet, lane, o);
    if (outf) {
        float4* op = (float4*)(outf + m * 256);
        op[lane * 2]     = make_float4(o[0], o[1], o[2], o[3]);
        op[lane * 2 + 1] = make_float4(o[4], o[5], o[6], o[7]);
    }
    if (outh) store_h8(outh + m * 256 + lane * 8, o);
}

// ---------------------------------------------------------------------------
// Fused LN3 + LN1(next layer); LN3 -> f32 xout, LN1 -> f16 lnb
// ---------------------------------------------------------------------------
__global__ void __launch_bounds__(256)
ln3ln1_kernel(const float* __restrict__ in,
              const float* __restrict__ res,
              const float* __restrict__ g3,
              const float* __restrict__ b3,
              const float* __restrict__ g1,
              const float* __restrict__ b1,
              float* __restrict__ xout,
              __half* __restrict__ lnb)
{
    int w = threadIdx.x >> 5, lane = threadIdx.x & 31;
    long m = (long)blockIdx.x * 8 + w;
    const float4* ip = (const float4*)(in + m * 256);
    const float4* rp = (const float4*)(res + m * 256);
    float4 v0 = ip[lane * 2], v1 = ip[lane * 2 + 1];
    float4 r0 = rp[lane * 2], r1 = rp[lane * 2 + 1];
    float a[8] = {v0.x + r0.x, v0.y + r0.y, v0.z + r0.z, v0.w + r0.w,
                  v1.x + r1.x, v1.y + r1.y, v1.z + r1.z, v1.w + r1.w};
    float o[8];
    warp_ln8(a, g3, b3, lane, o);
    float4* xp = (float4*)(xout + m * 256);
    xp[lane * 2]     = make_float4(o[0], o[1], o[2], o[3]);
    xp[lane * 2 + 1] = make_float4(o[4], o[5], o[6], o[7]);
    if (lnb) {
        float o2[8];
        warp_ln8(o, g1, b1, lane, o2);
        store_h8(lnb + m * 256 + lane * 8, o2);
    }
}

// ---------------------------------------------------------------------------
// FP16 GEMM core helpers (m16n8k16, A row-major [m][k], W transposed [n][k])
// ---------------------------------------------------------------------------
#define HMMA(acc, a0, a1, a2, a3, b0, b1)                                        \
    asm volatile(                                                                \
        "mma.sync.aligned.m16n8k16.row.col.f32.f16.f16.f32 "                     \
        "{%0,%1,%2,%3}, {%4,%5,%6,%7}, {%8,%9}, {%0,%1,%2,%3};\n"                \
        : "+f"(acc[0]), "+f"(acc[1]), "+f"(acc[2]), "+f"(acc[3])                 \
        : "r"(a0), "r"(a1), "r"(a2), "r"(a3), "r"(b0), "r"(b1))

// ---------------------------------------------------------------------------
// 128x128 tile fp16 GEMM. 256 thr, BK=32, 3-stage. AREV: reverse rows g==1.
// CH: C stored as half, else float. ACT: 0 none, 2 gelu.
// ---------------------------------------------------------------------------
template<int ACT, bool AREV, bool CH>
__global__ void __launch_bounds__(256, 2)
hf128_kernel(const __half* __restrict__ A, const __half* __restrict__ W,
             const float* __restrict__ bias, void* __restrict__ Cv,
             int M, int N, int K, int lda,
             long sAg, long sWg, long sCg)
{
    extern __shared__ __half dynh[];
    constexpr int AH = 128 * 40;
    constexpr int SH = AH + 128 * 40;

    int g = blockIdx.z;
    A += (long)g * sAg;
    W += (long)g * sWg;
    bool rev = AREV && (g == 1);

    int tid = threadIdx.x, warp = tid >> 5, lane = tid & 31;
    int wm = (warp & 1) * 64, wn = (warp >> 1) * 32;
    int gID = lane >> 2, tig = lane & 3;
    int rowBase = blockIdx.y * 128, colBase = blockIdx.x * 128;

    auto stage = [&](int buf, int k0) {
        __half* As = dynh + buf * SH;
        __half* Bs = As + AH;
#pragma unroll
        for (int it = 0; it < 2; it++) {
            int f = tid + it * 256;
            int r = f >> 2, c = (f & 3) * 8;
            int m = rowBase + r;
            if (rev) m = (m & ~511) + 511 - (m & 511);
            asm volatile("cp.async.ca.shared.global [%0], [%1], 16;\n"
                         :: "r"(smem_u32(&As[r * 40 + c])),
                            "l"(A + (long)m * lda + k0 + c));
        }
#pragma unroll
        for (int it = 0; it < 2; it++) {
            int f = tid + it * 256;
            int r = f >> 2, c = (f & 3) * 8;
            asm volatile("cp.async.ca.shared.global [%0], [%1], 16;\n"
                         :: "r"(smem_u32(&Bs[r * 40 + c])),
                            "l"(W + (long)(colBase + r) * K + k0 + c));
        }
        asm volatile("cp.async.commit_group;\n");
    };

    float acc[4][4][4];
#pragma unroll
    for (int a = 0; a < 4; a++)
#pragma unroll
        for (int b = 0; b < 4; b++)
#pragma unroll
            for (int c = 0; c < 4; c++) acc[a][b][c] = 0.f;

    auto compute = [&](int buf) {
        __half* As = dynh + buf * SH;
        __half* Bs = As + AH;
#pragma unroll
        for (int ks = 0; ks < 32; ks += 16) {
            uint32_t bf[4][2];
#pragma unroll
            for (int nt = 0; nt < 4; nt++) {
                int col = wn + nt * 8 + gID;
                bf[nt][0] = *(const uint32_t*)&Bs[col * 40 + ks + tig * 2];
                bf[nt][1] = *(const uint32_t*)&Bs[col * 40 + ks + tig * 2 + 8];
            }
#pragma unroll
            for (int mt = 0; mt < 4; mt++) {
                int row = wm + mt * 16 + gID;
                uint32_t a0 = *(const uint32_t*)&As[row * 40 + ks + tig * 2];
                uint32_t a1 = *(const uint32_t*)&As[(row + 8) * 40 + ks + tig * 2];
                uint32_t a2 = *(const uint32_t*)&As[row * 40 + ks + tig * 2 + 8];
                uint32_t a3 = *(const uint32_t*)&As[(row + 8) * 40 + ks + tig * 2 + 8];
#pragma unroll
                for (int nt = 0; nt < 4; nt++)
                    HMMA(acc[mt][nt], a0, a1, a2, a3, bf[nt][0], bf[nt][1]);
            }
        }
    };

    int nk = K >> 5;
    stage(0, 0);
    if (nk > 1) stage(1, 32);
    for (int ki = 0; ki < nk; ki++) {
        if (ki < nk - 1) asm volatile("cp.async.wait_group 1;\n");
        else             asm volatile("cp.async.wait_group 0;\n");
        __syncthreads();
        int kn = ki + 2;
        if (kn < nk) stage(kn % 3, kn << 5);
        compute(ki % 3);
    }

#pragma unroll
    for (int mt = 0; mt < 4; mt++) {
        int row0 = rowBase + wm + mt * 16 + gID;
#pragma unroll
        for (int nt = 0; nt < 4; nt++) {
            int col = colBase + wn + nt * 8 + tig * 2;
            float b0 = 0.f, b1 = 0.f;
            if (bias) { b0 = bias[col]; b1 = bias[col + 1]; }
            float v[4];
            v[0] = acc[mt][nt][0] + b0;
            v[1] = acc[mt][nt][1] + b1;
            v[2] = acc[mt][nt][2] + b0;
            v[3] = acc[mt][nt][3] + b1;
            if (ACT == 2) {
#pragma unroll
                for (int q = 0; q < 4; q++)
                    v[q] = 0.5f * v[q] * (1.f + erff(v[q] * 0.70710678118654752f));
            }
            if (CH) {
                __half* C = (__half*)Cv + (long)g * sCg;
                *(uint32_t*)&C[(long)row0 * N + col]       = h2u(v[0], v[1]);
                *(uint32_t*)&C[(long)(row0 + 8) * N + col] = h2u(v[2], v[3]);
            } else {
                float* C = (float*)Cv + (long)g * sCg;
                *(float2*)&C[(long)row0 * N + col]       = make_float2(v[0], v[1]);
                *(float2*)&C[(long)(row0 + 8) * N + col] = make_float2(v[2], v[3]);
            }
        }
    }
}

// ---------------------------------------------------------------------------
// 64x128 tile fp16 GEMM. NG: guarded N (colBase==0). DTF: fused dt. CH: C half.
// ---------------------------------------------------------------------------
template<int ACT, bool NG, bool DTF, bool CH>
__global__ void __launch_bounds__(256, 2)
hf64_kernel(const __half* __restrict__ A, const __half* __restrict__ W,
            const float* __restrict__ bias, void* __restrict__ Cv,
            int M, int N, int K, int lda,
            long sAg, long sWg, long sCg,
            const float* __restrict__ dtw,
            const float* __restrict__ dtb,
            float* __restrict__ DTout)
{
    extern __shared__ __half dynh[];
    constexpr int AH = 64 * 40;
    constexpr int SH = AH + 128 * 40;

    int g = blockIdx.z;
    A += (long)g * sAg;
    W += (long)g * sWg;
    if (DTF) {
        dtw += (long)g * 2048;
        dtb += (long)g * 256;
        DTout += (long)g * MT256;
    }

    int tid = threadIdx.x, warp = tid >> 5, lane = tid & 31;
    int wm = (warp & 1) * 32, wn = (warp >> 1) * 32;
    int gID = lane >> 2, tig = lane & 3;
    int rowBase = blockIdx.y * 64, colBase = blockIdx.x * 128;

    if (NG) {
#pragma unroll
        for (int s = 0; s < 3; s++) {
            __half* Bs = dynh + s * SH + AH;
            for (int f = tid; f < 512; f += 256) {
                int r = f >> 2, c = (f & 3) * 8;
                if (colBase + r >= N)
                    *(uint4*)&Bs[r * 40 + c] = make_uint4(0, 0, 0, 0);
            }
        }
        __syncthreads();
    }

    auto stage = [&](int buf, int k0) {
        __half* As = dynh + buf * SH;
        __half* Bs = As + AH;
        {
            int r = tid >> 2, c = (tid & 3) * 8;
            asm volatile("cp.async.ca.shared.global [%0], [%1], 16;\n"
                         :: "r"(smem_u32(&As[r * 40 + c])),
                            "l"(A + (long)(rowBase + r) * lda + k0 + c));
        }
#pragma unroll
        for (int it = 0; it < 2; it++) {
            int f = tid + it * 256;
            int r = f >> 2, c = (f & 3) * 8;
            if (!NG || colBase + r < N)
                asm volatile("cp.async.ca.shared.global [%0], [%1], 16;\n"
                             :: "r"(smem_u32(&Bs[r * 40 + c])),
                                "l"(W + (long)(colBase + r) * K + k0 + c));
        }
        asm volatile("cp.async.commit_group;\n");
    };

    float acc[2][4][4];
#pragma unroll
    for (int a = 0; a < 2; a++)
#pragma unroll
        for (int b = 0; b < 4; b++)
#pragma unroll
            for (int c = 0; c < 4; c++) acc[a][b][c] = 0.f;

    auto compute = [&](int buf) {
        __half* As = dynh + buf * SH;
        __half* Bs = As + AH;
#pragma unroll
        for (int ks = 0; ks < 32; ks += 16) {
            uint32_t bf[4][2];
#pragma unroll
            for (int nt = 0; nt < 4; nt++) {
                int col = wn + nt * 8 + gID;
                bf[nt][0] = *(const uint32_t*)&Bs[col * 40 + ks + tig * 2];
                bf[nt][1] = *(const uint32_t*)&Bs[col * 40 + ks + tig * 2 + 8];
            }
#pragma unroll
            for (int mt = 0; mt < 2; mt++) {
                int row = wm + mt * 16 + gID;
                uint32_t a0 = *(const uint32_t*)&As[row * 40 + ks + tig * 2];
                uint32_t a1 = *(const uint32_t*)&As[(row + 8) * 40 + ks + tig * 2];
                uint32_t a2 = *(const uint32_t*)&As[row * 40 + ks + tig * 2 + 8];
                uint32_t a3 = *(const uint32_t*)&As[(row + 8) * 40 + ks + tig * 2 + 8];
#pragma unroll
                for (int nt = 0; nt < 4; nt++)
                    HMMA(acc[mt][nt], a0, a1, a2, a3, bf[nt][0], bf[nt][1]);
            }
        }
    };

    int nk = K >> 5;
    stage(0, 0);
    if (nk > 1) stage(1, 32);
    for (int ki = 0; ki < nk; ki++) {
        if (ki < nk - 1) asm volatile("cp.async.wait_group 1;\n");
        else             asm volatile("cp.async.wait_group 0;\n");
        __syncthreads();
        int kn = ki + 2;
        if (kn < nk) stage(kn % 3, kn << 5);
        compute(ki % 3);
    }

#pragma unroll
    for (int mt = 0; mt < 2; mt++) {
        int row0 = rowBase + wm + mt * 16 + gID;
#pragma unroll
        for (int nt = 0; nt < 4; nt++) {
            int col = colBase + wn + nt * 8 + tig * 2;
            if (NG && col >= N) continue;
            float b0 = 0.f, b1 = 0.f;
            if (bias) { b0 = bias[col]; b1 = bias[col + 1]; }
            float v[4];
            v[0] = acc[mt][nt][0] + b0;
            v[1] = acc[mt][nt][1] + b1;
            v[2] = acc[mt][nt][2] + b0;
            v[3] = acc[mt][nt][3] + b1;
            if (ACT == 2) {
#pragma unroll
                for (int q = 0; q < 4; q++)
                    v[q] = 0.5f * v[q] * (1.f + erff(v[q] * 0.70710678118654752f));
            }
            if (CH) {
                __half* C = (__half*)Cv + (long)g * sCg;
                *(uint32_t*)&C[(long)row0 * N + col]       = h2u(v[0], v[1]);
                *(uint32_t*)&C[(long)(row0 + 8) * N + col] = h2u(v[2], v[3]);
            } else {
                float* C = (float*)Cv + (long)g * sCg;
                *(float2*)&C[(long)row0 * N + col]       = make_float2(v[0], v[1]);
                *(float2*)&C[(long)(row0 + 8) * N + col] = make_float2(v[2], v[3]);
            }
        }
    }

    if (DTF) {
        float* dbs = (float*)(dynh + 3 * SH);   // [64][8]
        if (warp < 2) {                         // wn==0 warps hold cols 0..7
            int col = tig * 2;
#pragma unroll
            for (int mt = 0; mt < 2; mt++) {
#pragma unroll
                for (int h = 0; h < 2; h++) {
                    int rl = wm + mt * 16 + gID + h * 8;
                    dbs[rl * 8 + col]     = acc[mt][0][h * 2];
                    dbs[rl * 8 + col + 1] = acc[mt][0][h * 2 + 1];
                }
            }
        }
        __syncthreads();
        int d = tid;
        float wreg[8];
#pragma unroll
        for (int r = 0; r < 8; r++) wreg[r] = dtw[r * 256 + d];
        float bb = dtb[d];
        float* dto = DTout + (long)rowBase * 256 + d;
        for (int r = 0; r < 64; r++) {
            float s = bb;
#pragma unroll
            for (int j = 0; j < 8; j++) s = fmaf(dbs[r * 8 + j], wreg[j], s);
            s = (s > 20.f) ? s : log1pf(expf(s));
            dto[(long)r * 256] = s;
        }
    }
}

// ---------------------------------------------------------------------------
// Fused out-projection (fp16): C = y0 @ Wc[0] + y1[rev] @ Wc[1] + bias (f32)
// 64x128 tile, 16 K-slabs (2 groups x 8). Wc transposed [2][256n][256k].
// ---------------------------------------------------------------------------
__global__ void __launch_bounds__(256, 2)
houtop_kernel(const __half* __restrict__ Y,
              const __half* __restrict__ Wc,
              const float* __restrict__ bias,
              float* __restrict__ C)
{
    extern __shared__ __half dynh[];
    constexpr int AH = 64 * 40;
    constexpr int SH = AH + 128 * 40;
    constexpr int N = 256;

    int tid = threadIdx.x, warp = tid >> 5, lane = tid & 31;
    int wm = (warp & 1) * 32, wn = (warp >> 1) * 32;
    int gID = lane >> 2, tig = lane & 3;
    int rowBase = blockIdx.y * 64, colBase = blockIdx.x * 128;

    auto stage = [&](int buf, int s) {
        int g = s >> 3;
        int k0 = (s & 7) << 5;
        const __half* Ab = Y + (long)g * MT256;
        const __half* Wb = Wc + (long)g * 65536;
        __half* As = dynh + buf * SH;
        __half* Bs = As + AH;
        {
            int r = tid >> 2, c = (tid & 3) * 8;
            int m = rowBase + r;
            if (g) m = (m & ~511) + 511 - (m & 511);
            asm volatile("cp.async.ca.shared.global [%0], [%1], 16;\n"
                         :: "r"(smem_u32(&As[r * 40 + c])),
                            "l"(Ab + (long)m * 256 + k0 + c));
        }
#pragma unroll
        for (int it = 0; it < 2; it++) {
            int f = tid + it * 256;
            int r = f >> 2, c = (f & 3) * 8;
            asm volatile("cp.async.ca.shared.global [%0], [%1], 16;\n"
                         :: "r"(smem_u32(&Bs[r * 40 + c])),
                            "l"(Wb + (long)(colBase + r) * 256 + k0 + c));
        }
        asm volatile("cp.async.commit_group;\n");
    };

    float acc[2][4][4];
#pragma unroll
    for (int a = 0; a < 2; a++)
#pragma unroll
        for (int b = 0; b < 4; b++)
#pragma unroll
            for (int c = 0; c < 4; c++) acc[a][b][c] = 0.f;

    auto compute = [&](int buf) {
        __half* As = dynh + buf * SH;
        __half* Bs = As + AH;
#pragma unroll
        for (int ks = 0; ks < 32; ks += 16) {
            uint32_t bf[4][2];
#pragma unroll
            for (int nt = 0; nt < 4; nt++) {
                int col = wn + nt * 8 + gID;
                bf[nt][0] = *(const uint32_t*)&Bs[col * 40 + ks + tig * 2];
                bf[nt][1] = *(const uint32_t*)&Bs[col * 40 + ks + tig * 2 + 8];
            }
#pragma unroll
            for (int mt = 0; mt < 2; mt++) {
                int row = wm + mt * 16 + gID;
                uint32_t a0 = *(const uint32_t*)&As[row * 40 + ks + tig * 2];
                uint32_t a1 = *(const uint32_t*)&As[(row + 8) * 40 + ks + tig * 2];
                uint32_t a2 = *(const uint32_t*)&As[row * 40 + ks + tig * 2 + 8];
                uint32_t a3 = *(const uint32_t*)&As[(row + 8) * 40 + ks + tig * 2 + 8];
#pragma unroll
                for (int nt = 0; nt < 4; nt++)
                    HMMA(acc[mt][nt], a0, a1, a2, a3, bf[nt][0], bf[nt][1]);
            }
        }
    };

    stage(0, 0);
    stage(1, 1);
    for (int s = 0; s < 16; s++) {
        if (s < 15) asm volatile("cp.async.wait_group 1;\n");
        else        asm volatile("cp.async.wait_group 0;\n");
        __syncthreads();
        int sn = s + 2;
        if (sn < 16) stage(sn % 3, sn);
        compute(s % 3);
    }

#pragma unroll
    for (int mt = 0; mt < 2; mt++) {
        int row0 = rowBase + wm + mt * 16 + gID;
#pragma unroll
        for (int nt = 0; nt < 4; nt++) {
            int col = colBase + wn + nt * 8 + tig * 2;
            float b0 = bias[col], b1 = bias[col + 1];
            *(float2*)&C[(long)row0 * N + col] =
                make_float2(acc[mt][nt][0] + b0, acc[mt][nt][1] + b1);
            *(float2*)&C[(long)(row0 + 8) * N + col] =
                make_float2(acc[mt][nt][2] + b0, acc[mt][nt][3] + b1);
        }
    }
}

// ---------------------------------------------------------------------------
// depthwise causal conv (K=4) + bias + silu; fp16 in/out; 4 t per thread
// ---------------------------------------------------------------------------
__global__ void conv_silu_kernel(const __half* __restrict__ xz,
                                 const float* __restrict__ convw,
                                 const float* __restrict__ convb,
                                 __half* __restrict__ xc)
{
    long i = (long)blockIdx.x * 256 + threadIdx.x;
    if (i >= 2 * MTOK * 64) return;
    int d = (int)(i & 255);
    long q = i >> 8;
    int t0 = (int)(q & 127) * 4;
    int b  = (int)((q >> 7) & 15);
    int g  = (int)(q >> 11);

    const float4 w4 = *(const float4*)(convw + ((long)g * 256 + d) * 4);
    float bias = convb[(long)g * 256 + d];

    long mrow = (long)g * MTOK + (long)b * 512 + t0;
    const __half* xp = xz + mrow * 512 + d;
    float xv[7];
#pragma unroll
    for (int j = 0; j < 7; j++) {
        int t = t0 - 3 + j;
        xv[j] = (t >= 0) ? __half2float(xp[(long)(j - 3) * 512]) : 0.f;
    }
    __half* op = xc + mrow * 256 + d;
#pragma unroll
    for (int j = 0; j < 4; j++) {
        float acc = bias;
        acc = fmaf(xv[j],     w4.x, acc);
        acc = fmaf(xv[j + 1], w4.y, acc);
        acc = fmaf(xv[j + 2], w4.z, acc);
        acc = fmaf(xv[j + 3], w4.w, acc);
        op[(long)j * 256] = __float2half(acc / (1.f + __expf(-acc)));
    }
}

// ---------------------------------------------------------------------------
// Selective scan, 8 lanes per (g,b,d) group, 2 states per lane, pipelined.
// xc/z fp16 inputs; y fp16 output; dt/dbc fp32.
// ---------------------------------------------------------------------------
__global__ void __launch_bounds__(256)
scan_kernel(const float* __restrict__ dt,
            const __half* __restrict__ xc,
            const float* __restrict__ dbc,
            const __half* __restrict__ xz,
            const float* __restrict__ alog,
            const float* __restrict__ dpar,
            __half* __restrict__ y)
{
    int gidx = blockIdx.x * 32 + (threadIdx.x >> 3);
    int li = threadIdx.x & 7;
    int g = gidx >> 12;
    int b = (gidx >> 8) & 15;
    int d = gidx & 255;

    const float2 al = *(const float2*)&alog[((long)(g * 256 + d)) * 16 + li * 2];
    const float L2E = 1.4426950408889634f;
    float A0 = -__expf(al.x) * L2E;
    float A1 = -__expf(al.y) * L2E;
    float dp = dpar[(long)g * 256 + d];

    long mbase = (long)g * MTOK + (long)b * 512;
    const float* dtp = dt + mbase * 256 + d;
    const __half* xcp = xc + mbase * 256 + d;
    const float* dbp = dbc + mbase * 40;
    const __half* zp = xz + mbase * 512 + 256 + d;
    __half* yp = y + mbase * 256 + d;

    float h0 = 0.f, h1 = 0.f;

    float dtv_n = dtp[0];
    float xv_n  = __half2float(xcp[0]);
    float z_n   = __half2float(zp[0]);
    float2 B_n  = *(const float2*)&dbp[8 + li * 2];
    float2 C_n  = *(const float2*)&dbp[24 + li * 2];

    for (int t = 0; t < 512; t++) {
        float dtv = dtv_n, xv = xv_n, z = z_n;
        float2 Bv = B_n, Cv = C_n;
        long tn = (t + 1 < 512) ? t + 1 : 511;
        dtv_n = dtp[tn * 256];
        xv_n  = __half2float(xcp[tn * 256]);
        z_n   = __half2float(zp[tn * 512]);
        B_n   = *(const float2*)&dbp[tn * 40 + 8 + li * 2];
        C_n   = *(const float2*)&dbp[tn * 40 + 24 + li * 2];

        float dx = dtv * xv;
        h0 = exp2f(dtv * A0) * h0 + dx * Bv.x;
        h1 = exp2f(dtv * A1) * h1 + dx * Bv.y;
        float p = h0 * Cv.x + h1 * Cv.y;
        p += __shfl_xor_sync(0xffffffffu, p, 4);
        p += __shfl_xor_sync(0xffffffffu, p, 2);
        p += __shfl_xor_sync(0xffffffffu, p, 1);
        if (li == 0) {
            float sz = z / (1.f + __expf(-z));
            yp[(long)t * 256] = __float2half((p + dp * xv) * sz);
        }
    }
}

// ---------------------------------------------------------------------------
// Launch helpers
// ---------------------------------------------------------------------------
constexpr int SMEM128 = 3 * (128 * 40 + 128 * 40) * 2;          // 61440 B
constexpr int SMEM64  = 3 * (64 * 40 + 128 * 40) * 2 + 2048;    // 48128 B

template<int ACT, bool AREV, bool CH>
static void launch_h128(const __half* A, const __half* W, const float* bias,
                        void* C, int M, int N, int K, int lda, int G,
                        long sAg, long sWg, long sCg)
{
    cudaFuncSetAttribute(hf128_kernel<ACT, AREV, CH>,
                         cudaFuncAttributeMaxDynamicSharedMemorySize, SMEM128);
    dim3 grid(N / 128, M / 128, G);
    hf128_kernel<ACT, AREV, CH><<<grid, 256, SMEM128>>>(A, W, bias, C, M, N, K,
                                                        lda, sAg, sWg, sCg);
}

template<int ACT, bool NG, bool DTF, bool CH>
static void launch_h64(const __half* A, const __half* W, const float* bias,
                       void* C, int M, int N, int K, int lda, int G,
                       long sAg, long sWg, long sCg,
                       const float* dtw = nullptr, const float* dtb = nullptr,
                       float* DTout = nullptr)
{
    cudaFuncSetAttribute(hf64_kernel<ACT, NG, DTF, CH>,
                         cudaFuncAttributeMaxDynamicSharedMemorySize, SMEM64);
    dim3 grid((N + 127) / 128, M / 64, G);
    hf64_kernel<ACT, NG, DTF, CH><<<grid, 256, SMEM64>>>(
        A, W, bias, C, M, N, K, lda, sAg, sWg, sCg, dtw, dtb, DTout);
}

static void launch_transcvt(const float* in, __half* out, int R, int C, int G,
                            long sIn, long sOut)
{
    dim3 grid((C + 31) / 32, (R + 31) / 32, G);
    transcvt_kernel<<<grid, dim3(32, 8)>>>(in, out, R, C, sIn, sOut);
}

extern "C" void kernel_launch(void* const* d_in, const int* in_sizes, int n_in,
                              void* d_out, int out_size)
{
    const float* input_ids = (const float*)d_in[0];
    const float* proj_w    = (const float*)d_in[1];
    const float* proj_b    = (const float*)d_in[2];
    const float* ln0_g     = (const float*)d_in[3];
    const float* ln0_b     = (const float*)d_in[4];
    const float* ln1_g     = (const float*)d_in[5];
    const float* ln1_b     = (const float*)d_in[6];
    const float* ip_w      = (const float*)d_in[7];
    const float* ip_b      = (const float*)d_in[8];
    const float* s_inw     = (const float*)d_in[9];
    const float* s_convw   = (const float*)d_in[10];
    const float* s_convb   = (const float*)d_in[11];
    const float* s_xw      = (const float*)d_in[12];
    const float* s_dtw     = (const float*)d_in[13];
    const float* s_dtb     = (const float*)d_in[14];
    const float* s_alog    = (const float*)d_in[15];
    const float* s_d       = (const float*)d_in[16];
    const float* s_outw    = (const float*)d_in[17];
    const float* op_w      = (const float*)d_in[18];
    const float* op_b      = (const float*)d_in[19];
    const float* ln2_g     = (const float*)d_in[20];
    const float* ln2_b     = (const float*)d_in[21];
    const float* f_w1      = (const float*)d_in[22];
    const float* f_b1      = (const float*)d_in[23];
    const float* f_w2      = (const float*)d_in[24];
    const float* f_b2      = (const float*)d_in[25];
    const float* ln3_g     = (const float*)d_in[26];
    const float* ln3_b     = (const float*)d_in[27];

    float* base = nullptr;
    cudaGetSymbolAddress((void**)&base, g_buf);

    float* X    = base + OFF_X;
    float* B256 = base + OFF_B256;
    float* DBC  = base + OFF_DBC;
    float* DT   = base + OFF_DT;
    float* W2C  = base + OFF_W2C;
    __half* hb  = (__half*)(base + OFF_HALF);
    __half* LNb = hb + HLNB;
    __half* Hb  = hb + HHB;
    __half* XZ  = hb + HXZ;
    __half* XC  = hb + HXC;
    __half* Y   = hb + HY;
    __half* Xh  = hb + HXH;
    __half* FF  = hb + HFF;
    __half* ipwT = hb + HIPWT;
    __half* inwT = hb + HINWT;
    __half* xwT  = hb + HXWT;
    __half* w1T  = hb + HW1T;
    __half* w2T  = hb + HW2T;
    __half* opwT = hb + HOPWT;
    __half* outwH = hb + HOUTW;
    __half* W2CT = hb + HW2CT;

    const int M = (int)MTOK;
    const int CONV_BLOCKS = (int)(2 * MTOK * 64 / 256);
    const int LN_BLOCKS = (int)(MTOK / 8);

    // --- weight precompute --------------------------------------------------
    cvt_kernel<<<(int)((24L * 32768 + 255) / 256), 256>>>(s_outw, outwH, 24L * 32768);
    launch_transcvt(op_w, opwT, 128, 256, 24, 32768, 32768);
    // compose W2C[g'] = outwH @ opwT  (fp16 GEMM, fp32 out)
    launch_h64<0, false, false, false>(outwH, opwT, nullptr, W2C,
                                       256, 256, 128, 128, 24,
                                       32768, 32768, 65536);
    launch_transcvt(W2C, W2CT, 256, 256, 24, 65536, 65536);
    launch_transcvt(ip_w, ipwT, 256, 256, 12, 65536, 65536);
    launch_transcvt(s_inw, inwT, 128, 512, 24, 65536, 65536);
    launch_transcvt(s_xw, xwT, 256, 40, 24, 10240, 10240);
    launch_transcvt(f_w1, w1T, 256, 1024, 12, 262144, 262144);
    launch_transcvt(f_w2, w2T, 1024, 256, 12, 262144, 262144);

    // --- embedding + first LN1 ----------------------------------------------
    embed_ln_kernel<<<M, 256>>>(input_ids, proj_w, proj_b, ln0_g, ln0_b, X);
    ln_kernel<<<LN_BLOCKS, 256>>>(X, nullptr, ln1_g, ln1_b, nullptr, LNb);

    for (int l = 0; l < 12; l++) {
        // in-proj h = LN1 @ ip_w + ip_b -> Hb (fp16)
        launch_h64<0, false, false, true>(LNb, ipwT + (long)l * 65536,
                                          ip_b + l * 256, Hb,
                                          M, 256, 256, 256, 1, 0, 0, 0);
        // xz = h-slice @ inw (col offset g*128, row reversal g=1) -> XZ fp16
        launch_h128<0, true, true>(Hb, inwT + (long)l * 131072, nullptr, XZ,
                                   M, 512, 128, 256, 2,
                                   128, 65536, MTOK * 512);
        // conv + silu
        conv_silu_kernel<<<CONV_BLOCKS, 256>>>(XZ, s_convw + (long)l * 2048,
                                               s_convb + (long)l * 512, XC);
        // dbc = xc @ xw (N=40 guarded) + fused dt
        launch_h64<0, true, true, false>(XC, xwT + (long)l * 20480, nullptr, DBC,
                                         M, 40, 256, 256, 2,
                                         MT256, 10240, MTOK * 40,
                                         s_dtw + (long)l * 4096,
                                         s_dtb + (long)l * 512, DT);
        // selective scan + fused silu(z) gate -> Y fp16
        scan_kernel<<<256, 256>>>(DT, XC, DBC, XZ,
                                  s_alog + (long)l * 8192,
                                  s_d + (long)l * 512, Y);
        // fused outw∘opw projection (+op_b) -> B256 fp32
        {
            cudaFuncSetAttribute(houtop_kernel,
                                 cudaFuncAttributeMaxDynamicSharedMemorySize, SMEM64);
            dim3 grid(2, M / 64, 1);
            houtop_kernel<<<grid, 256, SMEM64>>>(Y, W2CT + (long)l * 131072,
                                                 op_b + l * 256, B256);
        }
        // LN2 (residual) -> X fp32 + Xh fp16
        ln_kernel<<<LN_BLOCKS, 256>>>(B256, X, ln2_g + l * 256, ln2_b + l * 256,
                                      X, Xh);
        // ff = gelu(x @ w1 + b1) -> FF fp16
        launch_h128<2, false, true>(Xh, w1T + (long)l * 262144, f_b1 + l * 1024,
                                    FF, M, 1024, 256, 256, 1, 0, 0, 0);
        // f = ff @ w2 + b2 -> B256 fp32
        launch_h64<0, false, false, false>(FF, w2T + (long)l * 262144,
                                           f_b2 + l * 256, B256,
                                           M, 256, 1024, 1024, 1, 0, 0, 0);
        // LN3 fused with next layer's LN1
        float* dst = (l == 11) ? (float*)d_out : X;
        __half* lnb = (l == 11) ? nullptr : LNb;
        const float* g1 = ln1_g + (l + 1 < 12 ? (l + 1) * 256 : 0);
        const float* b1 = ln1_b + (l + 1 < 12 ? (l + 1) * 256 : 0);
        ln3ln1_kernel<<<LN_BLOCKS, 256>>>(B256, X, ln3_g + l * 256, ln3_b + l * 256,
                                          g1, b1, dst, lnb);
    }
}